// round 11
// baseline (speedup 1.0000x reference)
#include <cuda_runtime.h>
#include <cstdint>

// B=2, S=1024, H=1024, NH=16, HD=64, R=32, TOPK=128
#define TOPK 128

// device scratch (no allocation allowed)
__device__ __align__(16) float g_t[3u * 2048u * 1024u];         // tq,tk,tv
__device__ __align__(16) float g_xa[2048u * 256u];              // x @ [A0..A7]
__device__ __align__(16) float g_heads[8u * 32u * 1024u * 64u]; // [br][b*16+h][s][d]

// ---- Kernel 1: t_z = x @ W_z + b_z (two-level FFMA, 512 thr, 4x8 micro) ----
__global__ void __launch_bounds__(512) k_base_gemm(
    const float* __restrict__ x,
    const float* __restrict__ W0, const float* __restrict__ b0,
    const float* __restrict__ W1, const float* __restrict__ b1,
    const float* __restrict__ W2, const float* __restrict__ b2)
{
    const int z = blockIdx.z;
    const float* W    = (z == 0) ? W0 : ((z == 1) ? W1 : W2);
    const float* bias = (z == 0) ? b0 : ((z == 1) ? b1 : b2);
    float* C = g_t + (size_t)z * 2048u * 1024u;

    const int m0 = blockIdx.y * 128, n0 = blockIdx.x * 128;
    __shared__ __align__(16) float As[16][128];
    __shared__ __align__(16) float Bs[16][128];

    const int t = threadIdx.x, ty = t >> 4, tx = t & 15;
    float acc[4][8], part[4][8];
#pragma unroll
    for (int i = 0; i < 4; i++)
#pragma unroll
        for (int j = 0; j < 8; j++) acc[i][j] = 0.f;

    const int arow = t >> 2, akseg = (t & 3) * 4;   // A loader: 128 rows x 4 segs
    const int brow = t >> 5, bcol = (t & 31) * 4;   // B loader: 16 rows x 32 segs

    for (int kO = 0; kO < 1024; kO += 64) {
#pragma unroll
        for (int i = 0; i < 4; i++)
#pragma unroll
            for (int j = 0; j < 8; j++) part[i][j] = 0.f;

        for (int kt = 0; kt < 4; kt++) {
            const int k0 = kO + kt * 16;
            float4 av = *(const float4*)(x + (size_t)(m0 + arow) * 1024 + k0 + akseg);
            float4 bv = *(const float4*)(W + (size_t)(k0 + brow) * 1024 + n0 + bcol);
            As[akseg + 0][arow] = av.x; As[akseg + 1][arow] = av.y;
            As[akseg + 2][arow] = av.z; As[akseg + 3][arow] = av.w;
            *(float4*)&Bs[brow][bcol] = bv;
            __syncthreads();
#pragma unroll
            for (int kk = 0; kk < 16; kk++) {
                float a[4], b[8];
                *(float4*)&a[0] = *(const float4*)&As[kk][ty * 4];
                *(float4*)&b[0] = *(const float4*)&Bs[kk][tx * 8];
                *(float4*)&b[4] = *(const float4*)&Bs[kk][tx * 8 + 4];
#pragma unroll
                for (int i = 0; i < 4; i++)
#pragma unroll
                    for (int j = 0; j < 8; j++) part[i][j] += a[i] * b[j];
            }
            __syncthreads();
        }
#pragma unroll
        for (int i = 0; i < 4; i++)
#pragma unroll
            for (int j = 0; j < 8; j++) acc[i][j] += part[i][j];
    }
#pragma unroll
    for (int i = 0; i < 4; i++) {
        const int row = m0 + ty * 4 + i;
#pragma unroll
        for (int j4 = 0; j4 < 2; j4++) {
            const int col = n0 + tx * 8 + j4 * 4;
            float4 bb = *(const float4*)(bias + col);
            float4 o;
            o.x = acc[i][j4*4+0] + bb.x; o.y = acc[i][j4*4+1] + bb.y;
            o.z = acc[i][j4*4+2] + bb.z; o.w = acc[i][j4*4+3] + bb.w;
            *(float4*)(C + (size_t)row * 1024 + col) = o;
        }
    }
}

// ---------------- Kernel 2: xa[:, br*32:br*32+32] = x @ A_br ----------------
__global__ void __launch_bounds__(256) k_xa_gemm(
    const float* __restrict__ x,
    const float* A0, const float* A1, const float* A2, const float* A3,
    const float* A4, const float* A5, const float* A6, const float* A7)
{
    const int br = blockIdx.y;
    const float* A;
    switch (br) { case 0: A=A0; break; case 1: A=A1; break; case 2: A=A2; break; case 3: A=A3; break;
                  case 4: A=A4; break; case 5: A=A5; break; case 6: A=A6; break; default: A=A7; }
    const int m0 = blockIdx.x * 64;
    __shared__ float xs[32][64];
    __shared__ __align__(16) float as_[32][32];

    const int t = threadIdx.x;
    const int mm = t >> 2, rb = (t & 3) * 8;
    const int lm = t >> 2, lk = (t & 3) * 8;
    const int akk = t >> 3, ar = (t & 7) * 4;

    float acc[8];
#pragma unroll
    for (int j = 0; j < 8; j++) acc[j] = 0.f;

    for (int k0 = 0; k0 < 1024; k0 += 32) {
        float4 x0 = *(const float4*)(x + (size_t)(m0 + lm) * 1024 + k0 + lk);
        float4 x1 = *(const float4*)(x + (size_t)(m0 + lm) * 1024 + k0 + lk + 4);
        float4 a4 = *(const float4*)(A + (size_t)(k0 + akk) * 32 + ar);
        xs[lk+0][lm]=x0.x; xs[lk+1][lm]=x0.y; xs[lk+2][lm]=x0.z; xs[lk+3][lm]=x0.w;
        xs[lk+4][lm]=x1.x; xs[lk+5][lm]=x1.y; xs[lk+6][lm]=x1.z; xs[lk+7][lm]=x1.w;
        *(float4*)&as_[akk][ar] = a4;
        __syncthreads();
        float part[8];
#pragma unroll
        for (int j = 0; j < 8; j++) part[j] = 0.f;
#pragma unroll
        for (int kk = 0; kk < 32; kk++) {
            const float xv = xs[kk][mm];
#pragma unroll
            for (int j = 0; j < 8; j++) part[j] += xv * as_[kk][rb + j];
        }
#pragma unroll
        for (int j = 0; j < 8; j++) acc[j] += part[j];
        __syncthreads();
    }
    *(float4*)(g_xa + (size_t)(m0+mm)*256 + br*32 + rb)   = make_float4(acc[0],acc[1],acc[2],acc[3]);
    *(float4*)(g_xa + (size_t)(m0+mm)*256 + br*32 + rb+4) = make_float4(acc[4],acc[5],acc[6],acc[7]);
}

// ------- Kernel 3: heads[br] = base(br) + xa_br @ B_br, head layout -------
__global__ void __launch_bounds__(256) k_expand(
    const float* B0, const float* B1, const float* B2, const float* B3,
    const float* B4, const float* B5, const float* B6, const float* B7)
{
    const int br = blockIdx.z;
    const float* Bm;
    switch (br) { case 0: Bm=B0; break; case 1: Bm=B1; break; case 2: Bm=B2; break; case 3: Bm=B3; break;
                  case 4: Bm=B4; break; case 5: Bm=B5; break; case 6: Bm=B6; break; default: Bm=B7; }
    const int baseIdx = (br == 2 || br == 7) ? 2 : ((br == 1 || br == 4 || br == 6) ? 1 : 0);
    const float* tb = g_t + (size_t)baseIdx * 2048u * 1024u;

    const int m0 = blockIdx.y * 64, n0 = blockIdx.x * 64;
    __shared__ __align__(16) float xaS[32][68];
    __shared__ __align__(16) float bS[32][68];

    const int t = threadIdx.x;
    {
        const int m = t >> 2, rr = (t & 3) * 8;
        float4 v0 = *(const float4*)(g_xa + (size_t)(m0+m)*256 + br*32 + rr);
        float4 v1 = *(const float4*)(g_xa + (size_t)(m0+m)*256 + br*32 + rr + 4);
        xaS[rr+0][m]=v0.x; xaS[rr+1][m]=v0.y; xaS[rr+2][m]=v0.z; xaS[rr+3][m]=v0.w;
        xaS[rr+4][m]=v1.x; xaS[rr+5][m]=v1.y; xaS[rr+6][m]=v1.z; xaS[rr+7][m]=v1.w;
    }
    {
        const int r = t >> 3, nn = (t & 7) * 8;
        *(float4*)&bS[r][nn]   = *(const float4*)(Bm + (size_t)r*1024 + n0 + nn);
        *(float4*)&bS[r][nn+4] = *(const float4*)(Bm + (size_t)r*1024 + n0 + nn + 4);
    }
    __syncthreads();

    const int ty = t >> 4, tx = t & 15;
    float acc[4][4];
#pragma unroll
    for (int i = 0; i < 4; i++)
#pragma unroll
        for (int j = 0; j < 4; j++) acc[i][j] = 0.f;
#pragma unroll
    for (int r = 0; r < 32; r++) {
        float4 a4 = *(const float4*)&xaS[r][ty*4];
        float4 b4 = *(const float4*)&bS[r][tx*4];
        acc[0][0]+=a4.x*b4.x; acc[0][1]+=a4.x*b4.y; acc[0][2]+=a4.x*b4.z; acc[0][3]+=a4.x*b4.w;
        acc[1][0]+=a4.y*b4.x; acc[1][1]+=a4.y*b4.y; acc[1][2]+=a4.y*b4.z; acc[1][3]+=a4.y*b4.w;
        acc[2][0]+=a4.z*b4.x; acc[2][1]+=a4.z*b4.y; acc[2][2]+=a4.z*b4.z; acc[2][3]+=a4.z*b4.w;
        acc[3][0]+=a4.w*b4.x; acc[3][1]+=a4.w*b4.y; acc[3][2]+=a4.w*b4.z; acc[3][3]+=a4.w*b4.w;
    }

    const int h = blockIdx.x;
#pragma unroll
    for (int i = 0; i < 4; i++) {
        const int m = m0 + ty*4 + i, b_ = m >> 10, s = m & 1023;
        float4 base = *(const float4*)(tb + (size_t)m*1024 + n0 + tx*4);
        float4 o;
        o.x=acc[i][0]+base.x; o.y=acc[i][1]+base.y; o.z=acc[i][2]+base.z; o.w=acc[i][3]+base.w;
        *(float4*)(g_heads + (((size_t)br*32 + b_*16 + h)*1024 + s)*64 + tx*4) = o;
    }
}

// ---------------- Kernel 4: attention (exact R8 version, 1719.9 us) --------
__device__ __forceinline__ unsigned fmap(float f) {
    unsigned u = __float_as_uint(f);
    return (u & 0x80000000u) ? ~u : (u | 0x80000000u);
}
__device__ __forceinline__ float wredmax(float v) {
#pragma unroll
    for (int o = 16; o > 0; o >>= 1) v = fmaxf(v, __shfl_xor_sync(0xffffffffu, v, o));
    return v;
}
__device__ __forceinline__ float wredsum(float v) {
#pragma unroll
    for (int o = 16; o > 0; o >>= 1) v += __shfl_xor_sync(0xffffffffu, v, o);
    return v;
}
__device__ __forceinline__ unsigned wredsumu(unsigned v) {
#pragma unroll
    for (int o = 16; o > 0; o >>= 1) v += __shfl_xor_sync(0xffffffffu, v, o);
    return v;
}

// smem float offsets
#define OFF_KT   0
#define OFF_VT   8704              // 128*68
#define OFF_QV   (2*8704)          // 64*68
#define OFF_MASK (OFF_QV + 64*68)
#define OFF_PBUF (OFF_MASK + 1024) // 64*128
#define OFF_OB   (OFF_PBUF + 64*128)
#define OFF_OC   (OFF_OB + 64*68)
#define OFF_FAC  (OFF_OC + 64*68)
#define OFF_LSH  (OFF_FAC + 64)
#define OFF_KEEP (OFF_LSH + 64)    // 64*32 unsigned
#define SMEM_FLOATS (OFF_KEEP + 64*32)
#define SMEM_BYTES  (SMEM_FLOATS * 4)   // 167,424 B

template<bool KEEP>
__device__ void attn_phase(
    const int t,
    const float* __restrict__ qptr, const float* __restrict__ kptr,
    const float* __restrict__ vptr, const float* __restrict__ maskS,
    float* qv, float* ktile, float* vtile, float* pbuf,
    const unsigned* __restrict__ keepm, float* fac, float* l_sh, float* oacc)
{
    {   // load 64 query rows
        const int q = t >> 3, d = (t & 7) * 8;
        *(float4*)&qv[q*68 + d]     = *(const float4*)(qptr + (size_t)q*64 + d);
        *(float4*)&qv[q*68 + d + 4] = *(const float4*)(qptr + (size_t)q*64 + d + 4);
    }
    for (int i = t; i < 64*68; i += 512) oacc[i] = 0.f;

    float o[8][4];
#pragma unroll
    for (int i = 0; i < 8; i++)
#pragma unroll
        for (int j = 0; j < 4; j++) o[i][j] = 0.f;

    const int w  = t >> 5;                  // warp 0..15 -> queries 4w..4w+3
    const int kb = t & 31;                  // key slot
    const int dg = t & 15, kg = (t >> 4) & 3, qg = t >> 6;   // pv: queries 8qg..8qg+7
    float m_[4], l_[4];
#pragma unroll
    for (int qi = 0; qi < 4; qi++) { m_[qi] = -1e30f; l_[qi] = 0.f; }
    __syncthreads();

    for (int kt = 0; kt < 8; kt++) {
        {   // load K and V tiles: 512 threads, row t>>2, 16-float segment
            const int kloc = t >> 2, dd = (t & 3) * 16;
            const float* ksrc = kptr + ((size_t)kt*128 + kloc)*64 + dd;
            const float* vsrc = vptr + ((size_t)kt*128 + kloc)*64 + dd;
            float4 kr[4], vr[4];
#pragma unroll
            for (int jj = 0; jj < 4; jj++) kr[jj] = *(const float4*)(ksrc + jj*4);
#pragma unroll
            for (int jj = 0; jj < 4; jj++) vr[jj] = *(const float4*)(vsrc + jj*4);
            float* kdst = ktile + kloc*68 + dd;
            float* vdst = vtile + kloc*68 + dd;
#pragma unroll
            for (int jj = 0; jj < 4; jj++) *(float4*)(kdst + jj*4) = kr[jj];
#pragma unroll
            for (int jj = 0; jj < 4; jj++) *(float4*)(vdst + jj*4) = vr[jj];
        }
        __syncthreads();                    // S1

        // scores: 4 queries x 4 keys per thread (scalar accumulators)
        float s[4][4];
#pragma unroll
        for (int qi = 0; qi < 4; qi++)
#pragma unroll
            for (int j = 0; j < 4; j++) s[qi][j] = 0.f;
#pragma unroll
        for (int d4 = 0; d4 < 16; d4++) {
            float4 qf[4];
#pragma unroll
            for (int qi = 0; qi < 4; qi++)
                qf[qi] = *(const float4*)(qv + (4*w + qi)*68 + d4*4);
#pragma unroll
            for (int j = 0; j < 4; j++) {
                const float4 kf = *(const float4*)(ktile + (kb + 32*j)*68 + d4*4);
#pragma unroll
                for (int qi = 0; qi < 4; qi++)
                    s[qi][j] += qf[qi].x*kf.x + qf[qi].y*kf.y + qf[qi].z*kf.z + qf[qi].w*kf.w;
            }
        }
#pragma unroll
        for (int qi = 0; qi < 4; qi++) {
            bool kp[4];
            float tmx = -1e30f;
#pragma unroll
            for (int j = 0; j < 4; j++) {
                const int key = kt*128 + 32*j + kb;
                float sv = s[qi][j] * 0.125f + maskS[key];
                if (KEEP) {
                    kp[j] = (keepm[(4*w + qi)*32 + kt*4 + j] >> kb) & 1u;
                    if (!kp[j]) sv = -1e30f;
                } else kp[j] = true;
                s[qi][j] = sv;
                tmx = fmaxf(tmx, sv);
            }
            tmx = wredmax(tmx);
            const float nm = fmaxf(m_[qi], tmx);
            const float fr = __expf(m_[qi] - nm);
            m_[qi] = nm;
            if (kb == 0) fac[4*w + qi] = fr;
            float ps = 0.f;
#pragma unroll
            for (int j = 0; j < 4; j++) {
                float p = __expf(s[qi][j] - nm);
                if (KEEP && !kp[j]) p = 0.f;
                pbuf[(4*w + qi)*128 + 32*j + kb] = p;
                ps += p;
            }
            ps = wredsum(ps);
            l_[qi] = l_[qi] * fr + ps;
        }
        __syncthreads();                    // S2: fac + pbuf visible

        // pv: 8 queries per thread
        {
            float fq[8];
#pragma unroll
            for (int qi = 0; qi < 8; qi++) fq[qi] = fac[8*qg + qi];
#pragma unroll
            for (int qi = 0; qi < 8; qi++) {
                o[qi][0]*=fq[qi]; o[qi][1]*=fq[qi]; o[qi][2]*=fq[qi]; o[qi][3]*=fq[qi];
            }
#pragma unroll
            for (int kk4 = 0; kk4 < 8; kk4++) {
                const int base2 = kg*32 + kk4*4;
                const float4 v0 = *(const float4*)(vtile + (base2+0)*68 + dg*4);
                const float4 v1 = *(const float4*)(vtile + (base2+1)*68 + dg*4);
                const float4 v2 = *(const float4*)(vtile + (base2+2)*68 + dg*4);
                const float4 v3 = *(const float4*)(vtile + (base2+3)*68 + dg*4);
#pragma unroll
                for (int qi = 0; qi < 8; qi++) {
                    const float4 p4 = *(const float4*)(pbuf + (8*qg + qi)*128 + base2);
                    o[qi][0] += p4.x*v0.x + p4.y*v1.x + p4.z*v2.x + p4.w*v3.x;
                    o[qi][1] += p4.x*v0.y + p4.y*v1.y + p4.z*v2.y + p4.w*v3.y;
                    o[qi][2] += p4.x*v0.z + p4.y*v1.z + p4.z*v2.z + p4.w*v3.z;
                    o[qi][3] += p4.x*v0.w + p4.y*v1.w + p4.z*v2.w + p4.w*v3.w;
                }
            }
        }
        __syncthreads();                    // S3
    }

    if (kb == 0) {
#pragma unroll
        for (int qi = 0; qi < 4; qi++) l_sh[4*w + qi] = l_[qi];
    }
    for (int turn = 0; turn < 4; turn++) {
        if (kg == turn) {
#pragma unroll
            for (int qi = 0; qi < 8; qi++) {
                float* dst = oacc + (8*qg + qi)*68 + dg*4;
                dst[0]+=o[qi][0]; dst[1]+=o[qi][1]; dst[2]+=o[qi][2]; dst[3]+=o[qi][3];
            }
        }
        __syncthreads();
    }
    for (int i = t; i < 64*64; i += 512) {
        const int qq = i >> 6, d = i & 63;
        oacc[qq*68 + d] *= 0.5f / l_sh[qq];
    }
    __syncthreads();
}

__global__ void __launch_bounds__(512) k_attention(
    const float* __restrict__ am, float* __restrict__ out)
{
    extern __shared__ float smf[];
    float* ktile = smf + OFF_KT;
    float* vtile = smf + OFF_VT;
    float* qv    = smf + OFF_QV;
    float* maskS = smf + OFF_MASK;
    float* pbuf  = smf + OFF_PBUF;
    float* oaccB = smf + OFF_OB;
    float* oaccC = smf + OFF_OC;
    float* fac   = smf + OFF_FAC;
    float* l_sh  = smf + OFF_LSH;
    unsigned* keepm = (unsigned*)(smf + OFF_KEEP);

    const int t = threadIdx.x;
    const int head = blockIdx.y;        // b*16 + h
    const int q0 = blockIdx.x * 64;
    const int b_ = head >> 4;

    for (int i = t; i < 1024; i += 512) maskS[i] = am[b_*1024 + i];

    const size_t hs = (size_t)1024 * 64;
    const float* Tq  = g_heads + (0u*32 + head)*hs;
    const float* Tk  = g_heads + (1u*32 + head)*hs;
    const float* Tv  = g_heads + (2u*32 + head)*hs;
    const float* Tqs = g_heads + (3u*32 + head)*hs;
    const float* Tks = g_heads + (4u*32 + head)*hs;
    const float* Tqa = g_heads + (5u*32 + head)*hs;
    const float* Tka = g_heads + (6u*32 + head)*hs;
    const float* Tva = g_heads + (7u*32 + head)*hs;

    // ---- Phase A: qs.ks scores in registers, exact kth, keep bitmask ----
    {   // load 64 qs rows
        const int q = t >> 3, d = (t & 7) * 8;
        *(float4*)&qv[q*68 + d]     = *(const float4*)(Tqs + (size_t)(q0 + q)*64 + d);
        *(float4*)&qv[q*68 + d + 4] = *(const float4*)(Tqs + (size_t)(q0 + q)*64 + d + 4);
    }
    __syncthreads();

    const int qp = t >> 5, kb = t & 31;
#pragma unroll 1
    for (int pass = 0; pass < 2; pass++) {
        const int qA = pass*32 + 2*qp, qB = qA + 1;
        unsigned uv0[32], uv1[32];

        {   // prologue: tile 0 -> ktile
            const int kloc = t >> 2, dd = (t & 3) * 16;
            const float* src = Tks + (size_t)kloc*64 + dd;
            float* dst = ktile + kloc*68 + dd;
#pragma unroll
            for (int jj = 0; jj < 4; jj++) *(float4*)(dst + jj*4) = *(const float4*)(src + jj*4);
        }
        __syncthreads();

#pragma unroll 1
        for (int kt = 0; kt < 8; kt++) {
            float* cur = (kt & 1) ? vtile : ktile;
            float* nxt = (kt & 1) ? ktile : vtile;
            if (kt < 7) {   // prefetch next tile
                const int kloc = t >> 2, dd = (t & 3) * 16;
                const float* src = Tks + ((size_t)(kt+1)*128 + kloc)*64 + dd;
                float* dst = nxt + kloc*68 + dd;
#pragma unroll
                for (int jj = 0; jj < 4; jj++) *(float4*)(dst + jj*4) = *(const float4*)(src + jj*4);
            }
            float s0[4] = {0.f,0.f,0.f,0.f}, s1[4] = {0.f,0.f,0.f,0.f};
            const float4* q0v = (const float4*)(qv + qA*68);
            const float4* q1v = (const float4*)(qv + qB*68);
#pragma unroll
            for (int d4 = 0; d4 < 16; d4++) {
                const float4 f0 = q0v[d4], f1 = q1v[d4];
#pragma unroll
                for (int j = 0; j < 4; j++) {
                    const float4 kf = *(const float4*)(cur + (kb + 32*j)*68 + d4*4);
                    s0[j] += f0.x*kf.x + f0.y*kf.y + f0.z*kf.z + f0.w*kf.w;
                    s1[j] += f1.x*kf.x + f1.y*kf.y + f1.z*kf.z + f1.w*kf.w;
                }
            }
#pragma unroll
            for (int j = 0; j < 4; j++) {
                const float mv = maskS[kt*128 + 32*j + kb];
                uv0[kt*4+j] = fmap(s0[j] * 0.125f + mv);
                uv1[kt*4+j] = fmap(s1[j] * 0.125f + mv);
            }
            __syncthreads();
        }

        // dual exact kth-largest binary search (monotone uint space)
        unsigned lo0 = 0u, hi0 = 0xFFFFFFFFu, lo1 = 0u, hi1 = 0xFFFFFFFFu;
#pragma unroll 1
        for (int it = 0; it < 32; it++) {
            const unsigned d0 = hi0 - lo0, d1 = hi1 - lo1;
            const unsigned mid0 = lo0 + (d0 >> 1) + (d0 & 1u);
            const unsigned mid1 = lo1 + (d1 >> 1) + (d1 & 1u);
            unsigned c0 = 0, c1 = 0;
#pragma unroll
            for (int i = 0; i < 32; i++) {
                c0 += (uv0[i] >= mid0) ? 1u : 0u;
                c1 += (uv1[i] >= mid1) ? 1u : 0u;
            }
            const unsigned packed = wredsumu(c0 | (c1 << 16));
            const unsigned t0 = packed & 0xFFFFu, t1 = packed >> 16;
            if (t0 >= TOPK) lo0 = mid0; else hi0 = mid0 - 1u;
            if (t1 >= TOPK) lo1 = mid1; else hi1 = mid1 - 1u;
        }
#pragma unroll
        for (int i = 0; i < 32; i++) {
            const unsigned b0 = __ballot_sync(0xffffffffu, uv0[i] >= lo0);
            const unsigned b1 = __ballot_sync(0xffffffffu, uv1[i] >= lo1);
            if (kb == 0) { keepm[qA*32 + i] = b0; keepm[qB*32 + i] = b1; }
        }
        __syncthreads();
    }

    // ---- Phase B: est branch (dense softmax qa.ka, @ va) ----
    attn_phase<false>(t, Tqa + (size_t)q0*64, Tka, Tva, maskS,
                      qv, ktile, vtile, pbuf, keepm, fac, l_sh, oaccB);
    // ---- Phase C: sparse branch (keep-masked softmax q.k, @ v) ----
    attn_phase<true>(t, Tq + (size_t)q0*64, Tk, Tv, maskS,
                     qv, ktile, vtile, pbuf, keepm, fac, l_sh, oaccC);

    for (int i = t; i < 64*64; i += 512) {
        const int qq = i >> 6, d = i & 63;
        const float val = oaccB[qq*68 + d] + oaccC[qq*68 + d];
        out[((size_t)(b_*1024 + q0 + qq))*1024 + (head & 15)*64 + d] = val;
    }
}

// ---------------- host ----------------
extern "C" void kernel_launch(void* const* d_in, const int* in_sizes, int n_in,
                              void* d_out, int out_size) {
    const float* x  = (const float*)d_in[0];
    const float* am = (const float*)d_in[1];
    const float* Wq = (const float*)d_in[2]; const float* bq = (const float*)d_in[3];
    const float* Wk = (const float*)d_in[4]; const float* bk = (const float*)d_in[5];
    const float* Wv = (const float*)d_in[6]; const float* bv = (const float*)d_in[7];
    const float* A[8]; const float* Bm[8];
    for (int i = 0; i < 8; i++) { A[i] = (const float*)d_in[8 + 2*i]; Bm[i] = (const float*)d_in[9 + 2*i]; }
    float* out = (float*)d_out;

    cudaFuncSetAttribute(k_attention, cudaFuncAttributeMaxDynamicSharedMemorySize, SMEM_BYTES);

    k_base_gemm<<<dim3(8, 16, 3), 512>>>(x, Wq, bq, Wk, bk, Wv, bv);
    k_xa_gemm<<<dim3(32, 8), 256>>>(x, A[0],A[1],A[2],A[3],A[4],A[5],A[6],A[7]);
    k_expand<<<dim3(16, 32, 8), 256>>>(Bm[0],Bm[1],Bm[2],Bm[3],Bm[4],Bm[5],Bm[6],Bm[7]);
    k_attention<<<dim3(16, 32), 512, SMEM_BYTES>>>(am, out);
}

// round 12
// speedup vs baseline: 1.0982x; 1.0982x over previous
#include <cuda_runtime.h>
#include <cstdint>

// B=2, S=1024, H=1024, NH=16, HD=64, R=32, TOPK=128
#define TOPK 128

// device scratch (no allocation allowed)
__device__ __align__(16) float g_t[3u * 2048u * 1024u];         // tq,tk,tv
__device__ __align__(16) float g_xa[2048u * 256u];              // x @ [A0..A7]
__device__ __align__(16) float g_heads[8u * 32u * 1024u * 64u]; // [br][b*16+h][s][d]

// ---- Kernel 1: t_z = x @ W_z + b_z (two-level FFMA, double-buffered) ------
__global__ void __launch_bounds__(256) k_base_gemm(
    const float* __restrict__ x,
    const float* __restrict__ W0, const float* __restrict__ b0,
    const float* __restrict__ W1, const float* __restrict__ b1,
    const float* __restrict__ W2, const float* __restrict__ b2)
{
    const int z = blockIdx.z;
    const float* W    = (z == 0) ? W0 : ((z == 1) ? W1 : W2);
    const float* bias = (z == 0) ? b0 : ((z == 1) ? b1 : b2);
    float* C = g_t + (size_t)z * 2048u * 1024u;

    const int m0 = blockIdx.y * 128, n0 = blockIdx.x * 128;
    __shared__ __align__(16) float As[2][16][128];
    __shared__ __align__(16) float Bs[2][16][128];

    const int t = threadIdx.x, ty = t >> 4, tx = t & 15;
    float acc[8][8], part[8][8];
#pragma unroll
    for (int i = 0; i < 8; i++)
#pragma unroll
        for (int j = 0; j < 8; j++) { acc[i][j] = 0.f; part[i][j] = 0.f; }

    const int am = t >> 1, ak = (t & 1) * 8;
    const int bk = t >> 4, bn = (t & 15) * 8;

    {   // preload tile 0 into buffer 0
        float4 a0 = *(const float4*)(x + (size_t)(m0 + am) * 1024 + ak);
        float4 a1 = *(const float4*)(x + (size_t)(m0 + am) * 1024 + ak + 4);
        float4 w0 = *(const float4*)(W + (size_t)bk * 1024 + n0 + bn);
        float4 w1 = *(const float4*)(W + (size_t)bk * 1024 + n0 + bn + 4);
        As[0][ak + 0][am] = a0.x; As[0][ak + 1][am] = a0.y; As[0][ak + 2][am] = a0.z; As[0][ak + 3][am] = a0.w;
        As[0][ak + 4][am] = a1.x; As[0][ak + 5][am] = a1.y; As[0][ak + 6][am] = a1.z; As[0][ak + 7][am] = a1.w;
        *(float4*)&Bs[0][bk][bn] = w0;  *(float4*)&Bs[0][bk][bn + 4] = w1;
    }
    __syncthreads();

#pragma unroll 1
    for (int kt = 0; kt < 64; kt++) {
        const int cur = kt & 1, nxt = cur ^ 1;
        float4 a0n, a1n, w0n, w1n;
        if (kt < 63) {  // issue next-tile loads early (hidden under compute)
            const int k0 = (kt + 1) * 16;
            a0n = *(const float4*)(x + (size_t)(m0 + am) * 1024 + k0 + ak);
            a1n = *(const float4*)(x + (size_t)(m0 + am) * 1024 + k0 + ak + 4);
            w0n = *(const float4*)(W + (size_t)(k0 + bk) * 1024 + n0 + bn);
            w1n = *(const float4*)(W + (size_t)(k0 + bk) * 1024 + n0 + bn + 4);
        }
#pragma unroll
        for (int kk = 0; kk < 16; kk++) {
            float a[8], b[8];
            *(float4*)&a[0] = *(const float4*)&As[cur][kk][ty * 8];
            *(float4*)&a[4] = *(const float4*)&As[cur][kk][ty * 8 + 4];
            *(float4*)&b[0] = *(const float4*)&Bs[cur][kk][tx * 8];
            *(float4*)&b[4] = *(const float4*)&Bs[cur][kk][tx * 8 + 4];
#pragma unroll
            for (int i = 0; i < 8; i++)
#pragma unroll
                for (int j = 0; j < 8; j++) part[i][j] += a[i] * b[j];
        }
        if (kt < 63) {
            As[nxt][ak + 0][am] = a0n.x; As[nxt][ak + 1][am] = a0n.y;
            As[nxt][ak + 2][am] = a0n.z; As[nxt][ak + 3][am] = a0n.w;
            As[nxt][ak + 4][am] = a1n.x; As[nxt][ak + 5][am] = a1n.y;
            As[nxt][ak + 6][am] = a1n.z; As[nxt][ak + 7][am] = a1n.w;
            *(float4*)&Bs[nxt][bk][bn] = w0n;  *(float4*)&Bs[nxt][bk][bn + 4] = w1n;
        }
        if ((kt & 3) == 3) {    // fold every 64 K-steps (same order as R8)
#pragma unroll
            for (int i = 0; i < 8; i++)
#pragma unroll
                for (int j = 0; j < 8; j++) { acc[i][j] += part[i][j]; part[i][j] = 0.f; }
        }
        __syncthreads();
    }
#pragma unroll
    for (int i = 0; i < 8; i++) {
        const int row = m0 + ty * 8 + i;
#pragma unroll
        for (int j4 = 0; j4 < 2; j4++) {
            const int col = n0 + tx * 8 + j4 * 4;
            float4 bb = *(const float4*)(bias + col);
            float4 o;
            o.x = acc[i][j4*4+0] + bb.x; o.y = acc[i][j4*4+1] + bb.y;
            o.z = acc[i][j4*4+2] + bb.z; o.w = acc[i][j4*4+3] + bb.w;
            *(float4*)(C + (size_t)row * 1024 + col) = o;
        }
    }
}

// ---------------- Kernel 2: xa[:, br*32:br*32+32] = x @ A_br ----------------
__global__ void __launch_bounds__(256) k_xa_gemm(
    const float* __restrict__ x,
    const float* A0, const float* A1, const float* A2, const float* A3,
    const float* A4, const float* A5, const float* A6, const float* A7)
{
    const int br = blockIdx.y;
    const float* A;
    switch (br) { case 0: A=A0; break; case 1: A=A1; break; case 2: A=A2; break; case 3: A=A3; break;
                  case 4: A=A4; break; case 5: A=A5; break; case 6: A=A6; break; default: A=A7; }
    const int m0 = blockIdx.x * 64;
    __shared__ float xs[32][64];
    __shared__ __align__(16) float as_[32][32];

    const int t = threadIdx.x;
    const int mm = t >> 2, rb = (t & 3) * 8;
    const int lm = t >> 2, lk = (t & 3) * 8;
    const int akk = t >> 3, ar = (t & 7) * 4;

    float acc[8];
#pragma unroll
    for (int j = 0; j < 8; j++) acc[j] = 0.f;

    for (int k0 = 0; k0 < 1024; k0 += 32) {
        float4 x0 = *(const float4*)(x + (size_t)(m0 + lm) * 1024 + k0 + lk);
        float4 x1 = *(const float4*)(x + (size_t)(m0 + lm) * 1024 + k0 + lk + 4);
        float4 a4 = *(const float4*)(A + (size_t)(k0 + akk) * 32 + ar);
        xs[lk+0][lm]=x0.x; xs[lk+1][lm]=x0.y; xs[lk+2][lm]=x0.z; xs[lk+3][lm]=x0.w;
        xs[lk+4][lm]=x1.x; xs[lk+5][lm]=x1.y; xs[lk+6][lm]=x1.z; xs[lk+7][lm]=x1.w;
        *(float4*)&as_[akk][ar] = a4;
        __syncthreads();
        float part[8];
#pragma unroll
        for (int j = 0; j < 8; j++) part[j] = 0.f;
#pragma unroll
        for (int kk = 0; kk < 32; kk++) {
            const float xv = xs[kk][mm];
#pragma unroll
            for (int j = 0; j < 8; j++) part[j] += xv * as_[kk][rb + j];
        }
#pragma unroll
        for (int j = 0; j < 8; j++) acc[j] += part[j];
        __syncthreads();
    }
    *(float4*)(g_xa + (size_t)(m0+mm)*256 + br*32 + rb)   = make_float4(acc[0],acc[1],acc[2],acc[3]);
    *(float4*)(g_xa + (size_t)(m0+mm)*256 + br*32 + rb+4) = make_float4(acc[4],acc[5],acc[6],acc[7]);
}

// ------- Kernel 3: heads[br] = base(br) + xa_br @ B_br, head layout -------
__global__ void __launch_bounds__(256) k_expand(
    const float* B0, const float* B1, const float* B2, const float* B3,
    const float* B4, const float* B5, const float* B6, const float* B7)
{
    const int br = blockIdx.z;
    const float* Bm;
    switch (br) { case 0: Bm=B0; break; case 1: Bm=B1; break; case 2: Bm=B2; break; case 3: Bm=B3; break;
                  case 4: Bm=B4; break; case 5: Bm=B5; break; case 6: Bm=B6; break; default: Bm=B7; }
    const int baseIdx = (br == 2 || br == 7) ? 2 : ((br == 1 || br == 4 || br == 6) ? 1 : 0);
    const float* tb = g_t + (size_t)baseIdx * 2048u * 1024u;

    const int m0 = blockIdx.y * 64, n0 = blockIdx.x * 64;
    __shared__ __align__(16) float xaS[32][68];
    __shared__ __align__(16) float bS[32][68];

    const int t = threadIdx.x;
    {
        const int m = t >> 2, rr = (t & 3) * 8;
        float4 v0 = *(const float4*)(g_xa + (size_t)(m0+m)*256 + br*32 + rr);
        float4 v1 = *(const float4*)(g_xa + (size_t)(m0+m)*256 + br*32 + rr + 4);
        xaS[rr+0][m]=v0.x; xaS[rr+1][m]=v0.y; xaS[rr+2][m]=v0.z; xaS[rr+3][m]=v0.w;
        xaS[rr+4][m]=v1.x; xaS[rr+5][m]=v1.y; xaS[rr+6][m]=v1.z; xaS[rr+7][m]=v1.w;
    }
    {
        const int r = t >> 3, nn = (t & 7) * 8;
        *(float4*)&bS[r][nn]   = *(const float4*)(Bm + (size_t)r*1024 + n0 + nn);
        *(float4*)&bS[r][nn+4] = *(const float4*)(Bm + (size_t)r*1024 + n0 + nn + 4);
    }
    __syncthreads();

    const int ty = t >> 4, tx = t & 15;
    float acc[4][4];
#pragma unroll
    for (int i = 0; i < 4; i++)
#pragma unroll
        for (int j = 0; j < 4; j++) acc[i][j] = 0.f;
#pragma unroll
    for (int r = 0; r < 32; r++) {
        float4 a4 = *(const float4*)&xaS[r][ty*4];
        float4 b4 = *(const float4*)&bS[r][tx*4];
        acc[0][0]+=a4.x*b4.x; acc[0][1]+=a4.x*b4.y; acc[0][2]+=a4.x*b4.z; acc[0][3]+=a4.x*b4.w;
        acc[1][0]+=a4.y*b4.x; acc[1][1]+=a4.y*b4.y; acc[1][2]+=a4.y*b4.z; acc[1][3]+=a4.y*b4.w;
        acc[2][0]+=a4.z*b4.x; acc[2][1]+=a4.z*b4.y; acc[2][2]+=a4.z*b4.z; acc[2][3]+=a4.z*b4.w;
        acc[3][0]+=a4.w*b4.x; acc[3][1]+=a4.w*b4.y; acc[3][2]+=a4.w*b4.z; acc[3][3]+=a4.w*b4.w;
    }

    const int h = blockIdx.x;
#pragma unroll
    for (int i = 0; i < 4; i++) {
        const int m = m0 + ty*4 + i, b_ = m >> 10, s = m & 1023;
        float4 base = *(const float4*)(tb + (size_t)m*1024 + n0 + tx*4);
        float4 o;
        o.x=acc[i][0]+base.x; o.y=acc[i][1]+base.y; o.z=acc[i][2]+base.z; o.w=acc[i][3]+base.w;
        *(float4*)(g_heads + (((size_t)br*32 + b_*16 + h)*1024 + s)*64 + tx*4) = o;
    }
}

// ---------------- Kernel 4: attention (exact R8 version) --------------------
__device__ __forceinline__ unsigned fmap(float f) {
    unsigned u = __float_as_uint(f);
    return (u & 0x80000000u) ? ~u : (u | 0x80000000u);
}
__device__ __forceinline__ float wredmax(float v) {
#pragma unroll
    for (int o = 16; o > 0; o >>= 1) v = fmaxf(v, __shfl_xor_sync(0xffffffffu, v, o));
    return v;
}
__device__ __forceinline__ float wredsum(float v) {
#pragma unroll
    for (int o = 16; o > 0; o >>= 1) v += __shfl_xor_sync(0xffffffffu, v, o);
    return v;
}
__device__ __forceinline__ unsigned wredsumu(unsigned v) {
#pragma unroll
    for (int o = 16; o > 0; o >>= 1) v += __shfl_xor_sync(0xffffffffu, v, o);
    return v;
}

// smem float offsets
#define OFF_KT   0
#define OFF_VT   8704              // 128*68
#define OFF_QV   (2*8704)          // 64*68
#define OFF_MASK (OFF_QV + 64*68)
#define OFF_PBUF (OFF_MASK + 1024) // 64*128
#define OFF_OB   (OFF_PBUF + 64*128)
#define OFF_OC   (OFF_OB + 64*68)
#define OFF_FAC  (OFF_OC + 64*68)
#define OFF_LSH  (OFF_FAC + 64)
#define OFF_KEEP (OFF_LSH + 64)    // 64*32 unsigned
#define SMEM_FLOATS (OFF_KEEP + 64*32)
#define SMEM_BYTES  (SMEM_FLOATS * 4)   // 167,424 B

template<bool KEEP>
__device__ void attn_phase(
    const int t,
    const float* __restrict__ qptr, const float* __restrict__ kptr,
    const float* __restrict__ vptr, const float* __restrict__ maskS,
    float* qv, float* ktile, float* vtile, float* pbuf,
    const unsigned* __restrict__ keepm, float* fac, float* l_sh, float* oacc)
{
    {   // load 64 query rows
        const int q = t >> 3, d = (t & 7) * 8;
        *(float4*)&qv[q*68 + d]     = *(const float4*)(qptr + (size_t)q*64 + d);
        *(float4*)&qv[q*68 + d + 4] = *(const float4*)(qptr + (size_t)q*64 + d + 4);
    }
    for (int i = t; i < 64*68; i += 512) oacc[i] = 0.f;

    float o[8][4];
#pragma unroll
    for (int i = 0; i < 8; i++)
#pragma unroll
        for (int j = 0; j < 4; j++) o[i][j] = 0.f;

    const int w  = t >> 5;                  // warp 0..15 -> queries 4w..4w+3
    const int kb = t & 31;                  // key slot
    const int dg = t & 15, kg = (t >> 4) & 3, qg = t >> 6;   // pv: queries 8qg..8qg+7
    float m_[4], l_[4];
#pragma unroll
    for (int qi = 0; qi < 4; qi++) { m_[qi] = -1e30f; l_[qi] = 0.f; }
    __syncthreads();

    for (int kt = 0; kt < 8; kt++) {
        {   // load K and V tiles: 512 threads, row t>>2, 16-float segment
            const int kloc = t >> 2, dd = (t & 3) * 16;
            const float* ksrc = kptr + ((size_t)kt*128 + kloc)*64 + dd;
            const float* vsrc = vptr + ((size_t)kt*128 + kloc)*64 + dd;
            float4 kr[4], vr[4];
#pragma unroll
            for (int jj = 0; jj < 4; jj++) kr[jj] = *(const float4*)(ksrc + jj*4);
#pragma unroll
            for (int jj = 0; jj < 4; jj++) vr[jj] = *(const float4*)(vsrc + jj*4);
            float* kdst = ktile + kloc*68 + dd;
            float* vdst = vtile + kloc*68 + dd;
#pragma unroll
            for (int jj = 0; jj < 4; jj++) *(float4*)(kdst + jj*4) = kr[jj];
#pragma unroll
            for (int jj = 0; jj < 4; jj++) *(float4*)(vdst + jj*4) = vr[jj];
        }
        __syncthreads();                    // S1

        // scores: 4 queries x 4 keys per thread (scalar accumulators)
        float s[4][4];
#pragma unroll
        for (int qi = 0; qi < 4; qi++)
#pragma unroll
            for (int j = 0; j < 4; j++) s[qi][j] = 0.f;
#pragma unroll
        for (int d4 = 0; d4 < 16; d4++) {
            float4 qf[4];
#pragma unroll
            for (int qi = 0; qi < 4; qi++)
                qf[qi] = *(const float4*)(qv + (4*w + qi)*68 + d4*4);
#pragma unroll
            for (int j = 0; j < 4; j++) {
                const float4 kf = *(const float4*)(ktile + (kb + 32*j)*68 + d4*4);
#pragma unroll
                for (int qi = 0; qi < 4; qi++)
                    s[qi][j] += qf[qi].x*kf.x + qf[qi].y*kf.y + qf[qi].z*kf.z + qf[qi].w*kf.w;
            }
        }
#pragma unroll
        for (int qi = 0; qi < 4; qi++) {
            bool kp[4];
            float tmx = -1e30f;
#pragma unroll
            for (int j = 0; j < 4; j++) {
                const int key = kt*128 + 32*j + kb;
                float sv = s[qi][j] * 0.125f + maskS[key];
                if (KEEP) {
                    kp[j] = (keepm[(4*w + qi)*32 + kt*4 + j] >> kb) & 1u;
                    if (!kp[j]) sv = -1e30f;
                } else kp[j] = true;
                s[qi][j] = sv;
                tmx = fmaxf(tmx, sv);
            }
            tmx = wredmax(tmx);
            const float nm = fmaxf(m_[qi], tmx);
            const float fr = __expf(m_[qi] - nm);
            m_[qi] = nm;
            if (kb == 0) fac[4*w + qi] = fr;
            float ps = 0.f;
#pragma unroll
            for (int j = 0; j < 4; j++) {
                float p = __expf(s[qi][j] - nm);
                if (KEEP && !kp[j]) p = 0.f;
                pbuf[(4*w + qi)*128 + 32*j + kb] = p;
                ps += p;
            }
            ps = wredsum(ps);
            l_[qi] = l_[qi] * fr + ps;
        }
        __syncthreads();                    // S2: fac + pbuf visible

        // pv: 8 queries per thread
        {
            float fq[8];
#pragma unroll
            for (int qi = 0; qi < 8; qi++) fq[qi] = fac[8*qg + qi];
#pragma unroll
            for (int qi = 0; qi < 8; qi++) {
                o[qi][0]*=fq[qi]; o[qi][1]*=fq[qi]; o[qi][2]*=fq[qi]; o[qi][3]*=fq[qi];
            }
#pragma unroll
            for (int kk4 = 0; kk4 < 8; kk4++) {
                const int base2 = kg*32 + kk4*4;
                const float4 v0 = *(const float4*)(vtile + (base2+0)*68 + dg*4);
                const float4 v1 = *(const float4*)(vtile + (base2+1)*68 + dg*4);
                const float4 v2 = *(const float4*)(vtile + (base2+2)*68 + dg*4);
                const float4 v3 = *(const float4*)(vtile + (base2+3)*68 + dg*4);
#pragma unroll
                for (int qi = 0; qi < 8; qi++) {
                    const float4 p4 = *(const float4*)(pbuf + (8*qg + qi)*128 + base2);
                    o[qi][0] += p4.x*v0.x + p4.y*v1.x + p4.z*v2.x + p4.w*v3.x;
                    o[qi][1] += p4.x*v0.y + p4.y*v1.y + p4.z*v2.y + p4.w*v3.y;
                    o[qi][2] += p4.x*v0.z + p4.y*v1.z + p4.z*v2.z + p4.w*v3.z;
                    o[qi][3] += p4.x*v0.w + p4.y*v1.w + p4.z*v2.w + p4.w*v3.w;
                }
            }
        }
        __syncthreads();                    // S3
    }

    if (kb == 0) {
#pragma unroll
        for (int qi = 0; qi < 4; qi++) l_sh[4*w + qi] = l_[qi];
    }
    for (int turn = 0; turn < 4; turn++) {
        if (kg == turn) {
#pragma unroll
            for (int qi = 0; qi < 8; qi++) {
                float* dst = oacc + (8*qg + qi)*68 + dg*4;
                dst[0]+=o[qi][0]; dst[1]+=o[qi][1]; dst[2]+=o[qi][2]; dst[3]+=o[qi][3];
            }
        }
        __syncthreads();
    }
    for (int i = t; i < 64*64; i += 512) {
        const int qq = i >> 6, d = i & 63;
        oacc[qq*68 + d] *= 0.5f / l_sh[qq];
    }
    __syncthreads();
}

__global__ void __launch_bounds__(512) k_attention(
    const float* __restrict__ am, float* __restrict__ out)
{
    extern __shared__ float smf[];
    float* ktile = smf + OFF_KT;
    float* vtile = smf + OFF_VT;
    float* qv    = smf + OFF_QV;
    float* maskS = smf + OFF_MASK;
    float* pbuf  = smf + OFF_PBUF;
    float* oaccB = smf + OFF_OB;
    float* oaccC = smf + OFF_OC;
    float* fac   = smf + OFF_FAC;
    float* l_sh  = smf + OFF_LSH;
    unsigned* keepm = (unsigned*)(smf + OFF_KEEP);

    const int t = threadIdx.x;
    const int head = blockIdx.y;        // b*16 + h
    const int q0 = blockIdx.x * 64;
    const int b_ = head >> 4;

    for (int i = t; i < 1024; i += 512) maskS[i] = am[b_*1024 + i];

    const size_t hs = (size_t)1024 * 64;
    const float* Tq  = g_heads + (0u*32 + head)*hs;
    const float* Tk  = g_heads + (1u*32 + head)*hs;
    const float* Tv  = g_heads + (2u*32 + head)*hs;
    const float* Tqs = g_heads + (3u*32 + head)*hs;
    const float* Tks = g_heads + (4u*32 + head)*hs;
    const float* Tqa = g_heads + (5u*32 + head)*hs;
    const float* Tka = g_heads + (6u*32 + head)*hs;
    const float* Tva = g_heads + (7u*32 + head)*hs;

    // ---- Phase A: qs.ks scores in registers, exact kth, keep bitmask ----
    {   // load 64 qs rows
        const int q = t >> 3, d = (t & 7) * 8;
        *(float4*)&qv[q*68 + d]     = *(const float4*)(Tqs + (size_t)(q0 + q)*64 + d);
        *(float4*)&qv[q*68 + d + 4] = *(const float4*)(Tqs + (size_t)(q0 + q)*64 + d + 4);
    }
    __syncthreads();

    const int qp = t >> 5, kb = t & 31;
#pragma unroll 1
    for (int pass = 0; pass < 2; pass++) {
        const int qA = pass*32 + 2*qp, qB = qA + 1;
        unsigned uv0[32], uv1[32];

        {   // prologue: tile 0 -> ktile
            const int kloc = t >> 2, dd = (t & 3) * 16;
            const float* src = Tks + (size_t)kloc*64 + dd;
            float* dst = ktile + kloc*68 + dd;
#pragma unroll
            for (int jj = 0; jj < 4; jj++) *(float4*)(dst + jj*4) = *(const float4*)(src + jj*4);
        }
        __syncthreads();

#pragma unroll 1
        for (int kt = 0; kt < 8; kt++) {
            float* cur = (kt & 1) ? vtile : ktile;
            float* nxt = (kt & 1) ? ktile : vtile;
            if (kt < 7) {   // prefetch next tile
                const int kloc = t >> 2, dd = (t & 3) * 16;
                const float* src = Tks + ((size_t)(kt+1)*128 + kloc)*64 + dd;
                float* dst = nxt + kloc*68 + dd;
#pragma unroll
                for (int jj = 0; jj < 4; jj++) *(float4*)(dst + jj*4) = *(const float4*)(src + jj*4);
            }
            float s0[4] = {0.f,0.f,0.f,0.f}, s1[4] = {0.f,0.f,0.f,0.f};
            const float4* q0v = (const float4*)(qv + qA*68);
            const float4* q1v = (const float4*)(qv + qB*68);
#pragma unroll
            for (int d4 = 0; d4 < 16; d4++) {
                const float4 f0 = q0v[d4], f1 = q1v[d4];
#pragma unroll
                for (int j = 0; j < 4; j++) {
                    const float4 kf = *(const float4*)(cur + (kb + 32*j)*68 + d4*4);
                    s0[j] += f0.x*kf.x + f0.y*kf.y + f0.z*kf.z + f0.w*kf.w;
                    s1[j] += f1.x*kf.x + f1.y*kf.y + f1.z*kf.z + f1.w*kf.w;
                }
            }
#pragma unroll
            for (int j = 0; j < 4; j++) {
                const float mv = maskS[kt*128 + 32*j + kb];
                uv0[kt*4+j] = fmap(s0[j] * 0.125f + mv);
                uv1[kt*4+j] = fmap(s1[j] * 0.125f + mv);
            }
            __syncthreads();
        }

        // dual exact kth-largest binary search (monotone uint space)
        unsigned lo0 = 0u, hi0 = 0xFFFFFFFFu, lo1 = 0u, hi1 = 0xFFFFFFFFu;
#pragma unroll 1
        for (int it = 0; it < 32; it++) {
            const unsigned d0 = hi0 - lo0, d1 = hi1 - lo1;
            const unsigned mid0 = lo0 + (d0 >> 1) + (d0 & 1u);
            const unsigned mid1 = lo1 + (d1 >> 1) + (d1 & 1u);
            unsigned c0 = 0, c1 = 0;
#pragma unroll
            for (int i = 0; i < 32; i++) {
                c0 += (uv0[i] >= mid0) ? 1u : 0u;
                c1 += (uv1[i] >= mid1) ? 1u : 0u;
            }
            const unsigned packed = wredsumu(c0 | (c1 << 16));
            const unsigned t0 = packed & 0xFFFFu, t1 = packed >> 16;
            if (t0 >= TOPK) lo0 = mid0; else hi0 = mid0 - 1u;
            if (t1 >= TOPK) lo1 = mid1; else hi1 = mid1 - 1u;
        }
#pragma unroll
        for (int i = 0; i < 32; i++) {
            const unsigned b0 = __ballot_sync(0xffffffffu, uv0[i] >= lo0);
            const unsigned b1 = __ballot_sync(0xffffffffu, uv1[i] >= lo1);
            if (kb == 0) { keepm[qA*32 + i] = b0; keepm[qB*32 + i] = b1; }
        }
        __syncthreads();
    }

    // ---- Phase B: est branch (dense softmax qa.ka, @ va) ----
    attn_phase<false>(t, Tqa + (size_t)q0*64, Tka, Tva, maskS,
                      qv, ktile, vtile, pbuf, keepm, fac, l_sh, oaccB);
    // ---- Phase C: sparse branch (keep-masked softmax q.k, @ v) ----
    attn_phase<true>(t, Tq + (size_t)q0*64, Tk, Tv, maskS,
                     qv, ktile, vtile, pbuf, keepm, fac, l_sh, oaccC);

    for (int i = t; i < 64*64; i += 512) {
        const int qq = i >> 6, d = i & 63;
        const float val = oaccB[qq*68 + d] + oaccC[qq*68 + d];
        out[((size_t)(b_*1024 + q0 + qq))*1024 + (head & 15)*64 + d] = val;
    }
}

// ---------------- host ----------------
extern "C" void kernel_launch(void* const* d_in, const int* in_sizes, int n_in,
                              void* d_out, int out_size) {
    const float* x  = (const float*)d_in[0];
    const float* am = (const float*)d_in[1];
    const float* Wq = (const float*)d_in[2]; const float* bq = (const float*)d_in[3];
    const float* Wk = (const float*)d_in[4]; const float* bk = (const float*)d_in[5];
    const float* Wv = (const float*)d_in[6]; const float* bv = (const float*)d_in[7];
    const float* A[8]; const float* Bm[8];
    for (int i = 0; i < 8; i++) { A[i] = (const float*)d_in[8 + 2*i]; Bm[i] = (const float*)d_in[9 + 2*i]; }
    float* out = (float*)d_out;

    cudaFuncSetAttribute(k_attention, cudaFuncAttributeMaxDynamicSharedMemorySize, SMEM_BYTES);

    k_base_gemm<<<dim3(8, 16, 3), 256>>>(x, Wq, bq, Wk, bk, Wv, bv);
    k_xa_gemm<<<dim3(32, 8), 256>>>(x, A[0],A[1],A[2],A[3],A[4],A[5],A[6],A[7]);
    k_expand<<<dim3(16, 32, 8), 256>>>(Bm[0],Bm[1],Bm[2],Bm[3],Bm[4],Bm[5],Bm[6],Bm[7]);
    k_attention<<<dim3(16, 32), 512, SMEM_BYTES>>>(am, out);
}

// round 13
// speedup vs baseline: 1.1562x; 1.0528x over previous
#include <cuda_runtime.h>
#include <cstdint>

// B=2, S=1024, H=1024, NH=16, HD=64, R=32, TOPK=128
#define TOPK 128

// device scratch (no allocation allowed)
__device__ __align__(16) float g_t[3u * 2048u * 1024u];         // tq,tk,tv
__device__ __align__(16) float g_xa[2048u * 256u];              // x @ [A0..A7]
__device__ __align__(16) float g_heads[8u * 32u * 1024u * 64u]; // [br][b*16+h][s][d]
__device__ __align__(16) unsigned g_keep[32u * 16u * 64u * 32u]; // [head][qt][q][word]
__device__ __align__(16) float g_pb[2048u * 1024u];             // est-branch partial
__device__ __align__(16) float g_pc[2048u * 1024u];             // sparse-branch partial

// ---- Kernel 1: t_z = x @ W_z + b_z (two-level FFMA, double-buffered) ------
__global__ void __launch_bounds__(256) k_base_gemm(
    const float* __restrict__ x,
    const float* __restrict__ W0, const float* __restrict__ b0,
    const float* __restrict__ W1, const float* __restrict__ b1,
    const float* __restrict__ W2, const float* __restrict__ b2)
{
    const int z = blockIdx.z;
    const float* W    = (z == 0) ? W0 : ((z == 1) ? W1 : W2);
    const float* bias = (z == 0) ? b0 : ((z == 1) ? b1 : b2);
    float* C = g_t + (size_t)z * 2048u * 1024u;

    const int m0 = blockIdx.y * 128, n0 = blockIdx.x * 128;
    __shared__ __align__(16) float As[2][16][128];
    __shared__ __align__(16) float Bs[2][16][128];

    const int t = threadIdx.x, ty = t >> 4, tx = t & 15;
    float acc[8][8], part[8][8];
#pragma unroll
    for (int i = 0; i < 8; i++)
#pragma unroll
        for (int j = 0; j < 8; j++) { acc[i][j] = 0.f; part[i][j] = 0.f; }

    const int am = t >> 1, ak = (t & 1) * 8;
    const int bk = t >> 4, bn = (t & 15) * 8;

    {   // preload tile 0 into buffer 0
        float4 a0 = *(const float4*)(x + (size_t)(m0 + am) * 1024 + ak);
        float4 a1 = *(const float4*)(x + (size_t)(m0 + am) * 1024 + ak + 4);
        float4 w0 = *(const float4*)(W + (size_t)bk * 1024 + n0 + bn);
        float4 w1 = *(const float4*)(W + (size_t)bk * 1024 + n0 + bn + 4);
        As[0][ak + 0][am] = a0.x; As[0][ak + 1][am] = a0.y; As[0][ak + 2][am] = a0.z; As[0][ak + 3][am] = a0.w;
        As[0][ak + 4][am] = a1.x; As[0][ak + 5][am] = a1.y; As[0][ak + 6][am] = a1.z; As[0][ak + 7][am] = a1.w;
        *(float4*)&Bs[0][bk][bn] = w0;  *(float4*)&Bs[0][bk][bn + 4] = w1;
    }
    __syncthreads();

#pragma unroll 1
    for (int kt = 0; kt < 64; kt++) {
        const int cur = kt & 1, nxt = cur ^ 1;
        float4 a0n, a1n, w0n, w1n;
        if (kt < 63) {
            const int k0 = (kt + 1) * 16;
            a0n = *(const float4*)(x + (size_t)(m0 + am) * 1024 + k0 + ak);
            a1n = *(const float4*)(x + (size_t)(m0 + am) * 1024 + k0 + ak + 4);
            w0n = *(const float4*)(W + (size_t)(k0 + bk) * 1024 + n0 + bn);
            w1n = *(const float4*)(W + (size_t)(k0 + bk) * 1024 + n0 + bn + 4);
        }
#pragma unroll
        for (int kk = 0; kk < 16; kk++) {
            float a[8], b[8];
            *(float4*)&a[0] = *(const float4*)&As[cur][kk][ty * 8];
            *(float4*)&a[4] = *(const float4*)&As[cur][kk][ty * 8 + 4];
            *(float4*)&b[0] = *(const float4*)&Bs[cur][kk][tx * 8];
            *(float4*)&b[4] = *(const float4*)&Bs[cur][kk][tx * 8 + 4];
#pragma unroll
            for (int i = 0; i < 8; i++)
#pragma unroll
                for (int j = 0; j < 8; j++) part[i][j] += a[i] * b[j];
        }
        if (kt < 63) {
            As[nxt][ak + 0][am] = a0n.x; As[nxt][ak + 1][am] = a0n.y;
            As[nxt][ak + 2][am] = a0n.z; As[nxt][ak + 3][am] = a0n.w;
            As[nxt][ak + 4][am] = a1n.x; As[nxt][ak + 5][am] = a1n.y;
            As[nxt][ak + 6][am] = a1n.z; As[nxt][ak + 7][am] = a1n.w;
            *(float4*)&Bs[nxt][bk][bn] = w0n;  *(float4*)&Bs[nxt][bk][bn + 4] = w1n;
        }
        if ((kt & 3) == 3) {
#pragma unroll
            for (int i = 0; i < 8; i++)
#pragma unroll
                for (int j = 0; j < 8; j++) { acc[i][j] += part[i][j]; part[i][j] = 0.f; }
        }
        __syncthreads();
    }
#pragma unroll
    for (int i = 0; i < 8; i++) {
        const int row = m0 + ty * 8 + i;
#pragma unroll
        for (int j4 = 0; j4 < 2; j4++) {
            const int col = n0 + tx * 8 + j4 * 4;
            float4 bb = *(const float4*)(bias + col);
            float4 o;
            o.x = acc[i][j4*4+0] + bb.x; o.y = acc[i][j4*4+1] + bb.y;
            o.z = acc[i][j4*4+2] + bb.z; o.w = acc[i][j4*4+3] + bb.w;
            *(float4*)(C + (size_t)row * 1024 + col) = o;
        }
    }
}

// -------- Kernel 2: xa = x @ A_br (double-buffered) --------
__global__ void __launch_bounds__(256) k_xa_gemm(
    const float* __restrict__ x,
    const float* A0, const float* A1, const float* A2, const float* A3,
    const float* A4, const float* A5, const float* A6, const float* A7)
{
    const int br = blockIdx.y;
    const float* A;
    switch (br) { case 0: A=A0; break; case 1: A=A1; break; case 2: A=A2; break; case 3: A=A3; break;
                  case 4: A=A4; break; case 5: A=A5; break; case 6: A=A6; break; default: A=A7; }
    const int m0 = blockIdx.x * 64;
    __shared__ float xs[2][32][64];
    __shared__ __align__(16) float as_[2][32][32];

    const int t = threadIdx.x;
    const int mm = t >> 2, rb = (t & 3) * 8;
    const int lm = t >> 2, lk = (t & 3) * 8;
    const int akk = t >> 3, ar = (t & 7) * 4;

    float acc[8];
#pragma unroll
    for (int j = 0; j < 8; j++) acc[j] = 0.f;

    {   // preload tile 0
        float4 x0 = *(const float4*)(x + (size_t)(m0 + lm) * 1024 + lk);
        float4 x1 = *(const float4*)(x + (size_t)(m0 + lm) * 1024 + lk + 4);
        float4 a4 = *(const float4*)(A + (size_t)akk * 32 + ar);
        xs[0][lk+0][lm]=x0.x; xs[0][lk+1][lm]=x0.y; xs[0][lk+2][lm]=x0.z; xs[0][lk+3][lm]=x0.w;
        xs[0][lk+4][lm]=x1.x; xs[0][lk+5][lm]=x1.y; xs[0][lk+6][lm]=x1.z; xs[0][lk+7][lm]=x1.w;
        *(float4*)&as_[0][akk][ar] = a4;
    }
    __syncthreads();

#pragma unroll 1
    for (int kt = 0; kt < 32; kt++) {
        const int cur = kt & 1, nxt = cur ^ 1;
        float4 x0n, x1n, a4n;
        if (kt < 31) {
            const int k0 = (kt + 1) * 32;
            x0n = *(const float4*)(x + (size_t)(m0 + lm) * 1024 + k0 + lk);
            x1n = *(const float4*)(x + (size_t)(m0 + lm) * 1024 + k0 + lk + 4);
            a4n = *(const float4*)(A + (size_t)(k0 + akk) * 32 + ar);
        }
        float part[8];
#pragma unroll
        for (int j = 0; j < 8; j++) part[j] = 0.f;
#pragma unroll
        for (int kk = 0; kk < 32; kk++) {
            const float xv = xs[cur][kk][mm];
#pragma unroll
            for (int j = 0; j < 8; j++) part[j] += xv * as_[cur][kk][rb + j];
        }
#pragma unroll
        for (int j = 0; j < 8; j++) acc[j] += part[j];
        if (kt < 31) {
            xs[nxt][lk+0][lm]=x0n.x; xs[nxt][lk+1][lm]=x0n.y; xs[nxt][lk+2][lm]=x0n.z; xs[nxt][lk+3][lm]=x0n.w;
            xs[nxt][lk+4][lm]=x1n.x; xs[nxt][lk+5][lm]=x1n.y; xs[nxt][lk+6][lm]=x1n.z; xs[nxt][lk+7][lm]=x1n.w;
            *(float4*)&as_[nxt][akk][ar] = a4n;
        }
        __syncthreads();
    }
    *(float4*)(g_xa + (size_t)(m0+mm)*256 + br*32 + rb)   = make_float4(acc[0],acc[1],acc[2],acc[3]);
    *(float4*)(g_xa + (size_t)(m0+mm)*256 + br*32 + rb+4) = make_float4(acc[4],acc[5],acc[6],acc[7]);
}

// ------- Kernel 3: heads[br] = base(br) + xa_br @ B_br, head layout -------
__global__ void __launch_bounds__(256) k_expand(
    const float* B0, const float* B1, const float* B2, const float* B3,
    const float* B4, const float* B5, const float* B6, const float* B7)
{
    const int br = blockIdx.z;
    const float* Bm;
    switch (br) { case 0: Bm=B0; break; case 1: Bm=B1; break; case 2: Bm=B2; break; case 3: Bm=B3; break;
                  case 4: Bm=B4; break; case 5: Bm=B5; break; case 6: Bm=B6; break; default: Bm=B7; }
    const int baseIdx = (br == 2 || br == 7) ? 2 : ((br == 1 || br == 4 || br == 6) ? 1 : 0);
    const float* tb = g_t + (size_t)baseIdx * 2048u * 1024u;

    const int m0 = blockIdx.y * 64, n0 = blockIdx.x * 64;
    __shared__ __align__(16) float xaS[32][68];
    __shared__ __align__(16) float bS[32][68];

    const int t = threadIdx.x;
    {
        const int m = t >> 2, rr = (t & 3) * 8;
        float4 v0 = *(const float4*)(g_xa + (size_t)(m0+m)*256 + br*32 + rr);
        float4 v1 = *(const float4*)(g_xa + (size_t)(m0+m)*256 + br*32 + rr + 4);
        xaS[rr+0][m]=v0.x; xaS[rr+1][m]=v0.y; xaS[rr+2][m]=v0.z; xaS[rr+3][m]=v0.w;
        xaS[rr+4][m]=v1.x; xaS[rr+5][m]=v1.y; xaS[rr+6][m]=v1.z; xaS[rr+7][m]=v1.w;
    }
    {
        const int r = t >> 3, nn = (t & 7) * 8;
        *(float4*)&bS[r][nn]   = *(const float4*)(Bm + (size_t)r*1024 + n0 + nn);
        *(float4*)&bS[r][nn+4] = *(const float4*)(Bm + (size_t)r*1024 + n0 + nn + 4);
    }
    __syncthreads();

    const int ty = t >> 4, tx = t & 15;
    float acc[4][4];
#pragma unroll
    for (int i = 0; i < 4; i++)
#pragma unroll
        for (int j = 0; j < 4; j++) acc[i][j] = 0.f;
#pragma unroll
    for (int r = 0; r < 32; r++) {
        float4 a4 = *(const float4*)&xaS[r][ty*4];
        float4 b4 = *(const float4*)&bS[r][tx*4];
        acc[0][0]+=a4.x*b4.x; acc[0][1]+=a4.x*b4.y; acc[0][2]+=a4.x*b4.z; acc[0][3]+=a4.x*b4.w;
        acc[1][0]+=a4.y*b4.x; acc[1][1]+=a4.y*b4.y; acc[1][2]+=a4.y*b4.z; acc[1][3]+=a4.y*b4.w;
        acc[2][0]+=a4.z*b4.x; acc[2][1]+=a4.z*b4.y; acc[2][2]+=a4.z*b4.z; acc[2][3]+=a4.z*b4.w;
        acc[3][0]+=a4.w*b4.x; acc[3][1]+=a4.w*b4.y; acc[3][2]+=a4.w*b4.z; acc[3][3]+=a4.w*b4.w;
    }

    const int h = blockIdx.x;
#pragma unroll
    for (int i = 0; i < 4; i++) {
        const int m = m0 + ty*4 + i, b_ = m >> 10, s = m & 1023;
        float4 base = *(const float4*)(tb + (size_t)m*1024 + n0 + tx*4);
        float4 o;
        o.x=acc[i][0]+base.x; o.y=acc[i][1]+base.y; o.z=acc[i][2]+base.z; o.w=acc[i][3]+base.w;
        *(float4*)(g_heads + (((size_t)br*32 + b_*16 + h)*1024 + s)*64 + tx*4) = o;
    }
}

// ---------------- attention helpers ----------------
__device__ __forceinline__ unsigned fmap(float f) {
    unsigned u = __float_as_uint(f);
    return (u & 0x80000000u) ? ~u : (u | 0x80000000u);
}
__device__ __forceinline__ float wredmax(float v) {
#pragma unroll
    for (int o = 16; o > 0; o >>= 1) v = fmaxf(v, __shfl_xor_sync(0xffffffffu, v, o));
    return v;
}
__device__ __forceinline__ float wredsum(float v) {
#pragma unroll
    for (int o = 16; o > 0; o >>= 1) v += __shfl_xor_sync(0xffffffffu, v, o);
    return v;
}
__device__ __forceinline__ unsigned wredsumu(unsigned v) {
#pragma unroll
    for (int o = 16; o > 0; o >>= 1) v += __shfl_xor_sync(0xffffffffu, v, o);
    return v;
}

// ---------------- Kernel 4a: phase A (top-k keep bitmask) ----------------
#define A_OFF_KT   0
#define A_OFF_VT   8704
#define A_OFF_QV   (2*8704)
#define A_OFF_MASK (A_OFF_QV + 64*68)
#define A_SMEM_BYTES ((A_OFF_MASK + 1024) * 4)   // 91,136 B

__global__ void __launch_bounds__(512) k_attA(const float* __restrict__ am)
{
    extern __shared__ float smf[];
    float* ktile = smf + A_OFF_KT;
    float* vtile = smf + A_OFF_VT;
    float* qv    = smf + A_OFF_QV;
    float* maskS = smf + A_OFF_MASK;

    const int t = threadIdx.x;
    const int head = blockIdx.y;
    const int qt = blockIdx.x;
    const int q0 = qt * 64;
    const int b_ = head >> 4;

    for (int i = t; i < 1024; i += 512) maskS[i] = am[b_*1024 + i];

    const size_t hs = (size_t)1024 * 64;
    const float* Tqs = g_heads + (3u*32 + head)*hs;
    const float* Tks = g_heads + (4u*32 + head)*hs;

    {   // load 64 qs rows
        const int q = t >> 3, d = (t & 7) * 8;
        *(float4*)&qv[q*68 + d]     = *(const float4*)(Tqs + (size_t)(q0 + q)*64 + d);
        *(float4*)&qv[q*68 + d + 4] = *(const float4*)(Tqs + (size_t)(q0 + q)*64 + d + 4);
    }
    __syncthreads();

    const int qp = t >> 5, kb = t & 31;
    unsigned* gk = g_keep + (((size_t)head*16 + qt)*64)*32;
#pragma unroll 1
    for (int pass = 0; pass < 2; pass++) {
        const int qA = pass*32 + 2*qp, qB = qA + 1;
        unsigned uv0[32], uv1[32];

        {   // prologue: tile 0 -> ktile
            const int kloc = t >> 2, dd = (t & 3) * 16;
            const float* src = Tks + (size_t)kloc*64 + dd;
            float* dst = ktile + kloc*68 + dd;
#pragma unroll
            for (int jj = 0; jj < 4; jj++) *(float4*)(dst + jj*4) = *(const float4*)(src + jj*4);
        }
        __syncthreads();

#pragma unroll 1
        for (int kt = 0; kt < 8; kt++) {
            float* cur = (kt & 1) ? vtile : ktile;
            float* nxt = (kt & 1) ? ktile : vtile;
            if (kt < 7) {
                const int kloc = t >> 2, dd = (t & 3) * 16;
                const float* src = Tks + ((size_t)(kt+1)*128 + kloc)*64 + dd;
                float* dst = nxt + kloc*68 + dd;
#pragma unroll
                for (int jj = 0; jj < 4; jj++) *(float4*)(dst + jj*4) = *(const float4*)(src + jj*4);
            }
            float s0[4] = {0.f,0.f,0.f,0.f}, s1[4] = {0.f,0.f,0.f,0.f};
            const float4* q0v = (const float4*)(qv + qA*68);
            const float4* q1v = (const float4*)(qv + qB*68);
#pragma unroll
            for (int d4 = 0; d4 < 16; d4++) {
                const float4 f0 = q0v[d4], f1 = q1v[d4];
#pragma unroll
                for (int j = 0; j < 4; j++) {
                    const float4 kf = *(const float4*)(cur + (kb + 32*j)*68 + d4*4);
                    s0[j] += f0.x*kf.x + f0.y*kf.y + f0.z*kf.z + f0.w*kf.w;
                    s1[j] += f1.x*kf.x + f1.y*kf.y + f1.z*kf.z + f1.w*kf.w;
                }
            }
#pragma unroll
            for (int j = 0; j < 4; j++) {
                const float mv = maskS[kt*128 + 32*j + kb];
                uv0[kt*4+j] = fmap(s0[j] * 0.125f + mv);
                uv1[kt*4+j] = fmap(s1[j] * 0.125f + mv);
            }
            __syncthreads();
        }

        unsigned lo0 = 0u, hi0 = 0xFFFFFFFFu, lo1 = 0u, hi1 = 0xFFFFFFFFu;
#pragma unroll 1
        for (int it = 0; it < 32; it++) {
            const unsigned d0 = hi0 - lo0, d1 = hi1 - lo1;
            const unsigned mid0 = lo0 + (d0 >> 1) + (d0 & 1u);
            const unsigned mid1 = lo1 + (d1 >> 1) + (d1 & 1u);
            unsigned c0 = 0, c1 = 0;
#pragma unroll
            for (int i = 0; i < 32; i++) {
                c0 += (uv0[i] >= mid0) ? 1u : 0u;
                c1 += (uv1[i] >= mid1) ? 1u : 0u;
            }
            const unsigned packed = wredsumu(c0 | (c1 << 16));
            const unsigned t0 = packed & 0xFFFFu, t1 = packed >> 16;
            if (t0 >= TOPK) lo0 = mid0; else hi0 = mid0 - 1u;
            if (t1 >= TOPK) lo1 = mid1; else hi1 = mid1 - 1u;
        }
#pragma unroll
        for (int i = 0; i < 32; i++) {
            const unsigned b0 = __ballot_sync(0xffffffffu, uv0[i] >= lo0);
            const unsigned b1 = __ballot_sync(0xffffffffu, uv1[i] >= lo1);
            if (kb == 0) { gk[qA*32 + i] = b0; gk[qB*32 + i] = b1; }
        }
        __syncthreads();
    }
}

// ---------------- Kernel 4b: phases B/C (z selects branch) ----------------
#define OFF_KT   0
#define OFF_VT   8704
#define OFF_QV   (2*8704)
#define OFF_MASK (OFF_QV + 64*68)
#define OFF_PBUF (OFF_MASK + 1024)
#define OFF_OA   (OFF_PBUF + 64*128)
#define OFF_FAC  (OFF_OA + 64*68)
#define OFF_LSH  (OFF_FAC + 64)
#define OFF_KEEP (OFF_LSH + 64)
#define BC_SMEM_BYTES ((OFF_KEEP + 64*32) * 4)   // 150,016 B

template<bool KEEP>
__device__ void attn_phase(
    const int t,
    const float* __restrict__ qptr, const float* __restrict__ kptr,
    const float* __restrict__ vptr, const float* __restrict__ maskS,
    float* qv, float* ktile, float* vtile, float* pbuf,
    const unsigned* __restrict__ keepm, float* fac, float* l_sh, float* oacc)
{
    {
        const int q = t >> 3, d = (t & 7) * 8;
        *(float4*)&qv[q*68 + d]     = *(const float4*)(qptr + (size_t)q*64 + d);
        *(float4*)&qv[q*68 + d + 4] = *(const float4*)(qptr + (size_t)q*64 + d + 4);
    }
    for (int i = t; i < 64*68; i += 512) oacc[i] = 0.f;

    float o[8][4];
#pragma unroll
    for (int i = 0; i < 8; i++)
#pragma unroll
        for (int j = 0; j < 4; j++) o[i][j] = 0.f;

    const int w  = t >> 5;
    const int kb = t & 31;
    const int dg = t & 15, kg = (t >> 4) & 3, qg = t >> 6;
    float m_[4], l_[4];
#pragma unroll
    for (int qi = 0; qi < 4; qi++) { m_[qi] = -1e30f; l_[qi] = 0.f; }
    __syncthreads();

    for (int kt = 0; kt < 8; kt++) {
        {
            const int kloc = t >> 2, dd = (t & 3) * 16;
            const float* ksrc = kptr + ((size_t)kt*128 + kloc)*64 + dd;
            const float* vsrc = vptr + ((size_t)kt*128 + kloc)*64 + dd;
            float4 kr[4], vr[4];
#pragma unroll
            for (int jj = 0; jj < 4; jj++) kr[jj] = *(const float4*)(ksrc + jj*4);
#pragma unroll
            for (int jj = 0; jj < 4; jj++) vr[jj] = *(const float4*)(vsrc + jj*4);
            float* kdst = ktile + kloc*68 + dd;
            float* vdst = vtile + kloc*68 + dd;
#pragma unroll
            for (int jj = 0; jj < 4; jj++) *(float4*)(kdst + jj*4) = kr[jj];
#pragma unroll
            for (int jj = 0; jj < 4; jj++) *(float4*)(vdst + jj*4) = vr[jj];
        }
        __syncthreads();

        float s[4][4];
#pragma unroll
        for (int qi = 0; qi < 4; qi++)
#pragma unroll
            for (int j = 0; j < 4; j++) s[qi][j] = 0.f;
#pragma unroll
        for (int d4 = 0; d4 < 16; d4++) {
            float4 qf[4];
#pragma unroll
            for (int qi = 0; qi < 4; qi++)
                qf[qi] = *(const float4*)(qv + (4*w + qi)*68 + d4*4);
#pragma unroll
            for (int j = 0; j < 4; j++) {
                const float4 kf = *(const float4*)(ktile + (kb + 32*j)*68 + d4*4);
#pragma unroll
                for (int qi = 0; qi < 4; qi++)
                    s[qi][j] += qf[qi].x*kf.x + qf[qi].y*kf.y + qf[qi].z*kf.z + qf[qi].w*kf.w;
            }
        }
#pragma unroll
        for (int qi = 0; qi < 4; qi++) {
            bool kp[4];
            float tmx = -1e30f;
#pragma unroll
            for (int j = 0; j < 4; j++) {
                const int key = kt*128 + 32*j + kb;
                float sv = s[qi][j] * 0.125f + maskS[key];
                if (KEEP) {
                    kp[j] = (keepm[(4*w + qi)*32 + kt*4 + j] >> kb) & 1u;
                    if (!kp[j]) sv = -1e30f;
                } else kp[j] = true;
                s[qi][j] = sv;
                tmx = fmaxf(tmx, sv);
            }
            tmx = wredmax(tmx);
            const float nm = fmaxf(m_[qi], tmx);
            const float fr = __expf(m_[qi] - nm);
            m_[qi] = nm;
            if (kb == 0) fac[4*w + qi] = fr;
            float ps = 0.f;
#pragma unroll
            for (int j = 0; j < 4; j++) {
                float p = __expf(s[qi][j] - nm);
                if (KEEP && !kp[j]) p = 0.f;
                pbuf[(4*w + qi)*128 + 32*j + kb] = p;
                ps += p;
            }
            ps = wredsum(ps);
            l_[qi] = l_[qi] * fr + ps;
        }
        __syncthreads();

        {
            float fq[8];
#pragma unroll
            for (int qi = 0; qi < 8; qi++) fq[qi] = fac[8*qg + qi];
#pragma unroll
            for (int qi = 0; qi < 8; qi++) {
                o[qi][0]*=fq[qi]; o[qi][1]*=fq[qi]; o[qi][2]*=fq[qi]; o[qi][3]*=fq[qi];
            }
#pragma unroll
            for (int kk4 = 0; kk4 < 8; kk4++) {
                const int base2 = kg*32 + kk4*4;
                const float4 v0 = *(const float4*)(vtile + (base2+0)*68 + dg*4);
                const float4 v1 = *(const float4*)(vtile + (base2+1)*68 + dg*4);
                const float4 v2 = *(const float4*)(vtile + (base2+2)*68 + dg*4);
                const float4 v3 = *(const float4*)(vtile + (base2+3)*68 + dg*4);
#pragma unroll
                for (int qi = 0; qi < 8; qi++) {
                    const float4 p4 = *(const float4*)(pbuf + (8*qg + qi)*128 + base2);
                    o[qi][0] += p4.x*v0.x + p4.y*v1.x + p4.z*v2.x + p4.w*v3.x;
                    o[qi][1] += p4.x*v0.y + p4.y*v1.y + p4.z*v2.y + p4.w*v3.y;
                    o[qi][2] += p4.x*v0.z + p4.y*v1.z + p4.z*v2.z + p4.w*v3.z;
                    o[qi][3] += p4.x*v0.w + p4.y*v1.w + p4.z*v2.w + p4.w*v3.w;
                }
            }
        }
        __syncthreads();
    }

    if (kb == 0) {
#pragma unroll
        for (int qi = 0; qi < 4; qi++) l_sh[4*w + qi] = l_[qi];
    }
    for (int turn = 0; turn < 4; turn++) {
        if (kg == turn) {
#pragma unroll
            for (int qi = 0; qi < 8; qi++) {
                float* dst = oacc + (8*qg + qi)*68 + dg*4;
                dst[0]+=o[qi][0]; dst[1]+=o[qi][1]; dst[2]+=o[qi][2]; dst[3]+=o[qi][3];
            }
        }
        __syncthreads();
    }
    for (int i = t; i < 64*64; i += 512) {
        const int qq = i >> 6, d = i & 63;
        oacc[qq*68 + d] *= 0.5f / l_sh[qq];
    }
    __syncthreads();
}

__global__ void __launch_bounds__(512) k_attBC(const float* __restrict__ am)
{
    extern __shared__ float smf[];
    float* ktile = smf + OFF_KT;
    float* vtile = smf + OFF_VT;
    float* qv    = smf + OFF_QV;
    float* maskS = smf + OFF_MASK;
    float* pbuf  = smf + OFF_PBUF;
    float* oacc  = smf + OFF_OA;
    float* fac   = smf + OFF_FAC;
    float* l_sh  = smf + OFF_LSH;
    unsigned* keepm = (unsigned*)(smf + OFF_KEEP);

    const int t = threadIdx.x;
    const int head = blockIdx.y;
    const int qt = blockIdx.x;
    const int q0 = qt * 64;
    const int b_ = head >> 4;
    const int z = blockIdx.z;       // 0 = est branch, 1 = sparse branch

    for (int i = t; i < 1024; i += 512) maskS[i] = am[b_*1024 + i];

    const size_t hs = (size_t)1024 * 64;
    const float *Tq_, *Tk_, *Tv_;
    float* dstPart;
    if (z == 0) {
        Tq_ = g_heads + (5u*32 + head)*hs;  // qa
        Tk_ = g_heads + (6u*32 + head)*hs;  // ka
        Tv_ = g_heads + (7u*32 + head)*hs;  // va
        dstPart = g_pb;
    } else {
        Tq_ = g_heads + (0u*32 + head)*hs;  // q
        Tk_ = g_heads + (1u*32 + head)*hs;  // k
        Tv_ = g_heads + (2u*32 + head)*hs;  // v
        dstPart = g_pc;
        const unsigned* gk = g_keep + (((size_t)head*16 + qt)*64)*32;
        for (int i = t; i < 64*32; i += 512) keepm[i] = gk[i];
    }
    __syncthreads();

    if (z == 0)
        attn_phase<false>(t, Tq_ + (size_t)q0*64, Tk_, Tv_, maskS,
                          qv, ktile, vtile, pbuf, keepm, fac, l_sh, oacc);
    else
        attn_phase<true>(t, Tq_ + (size_t)q0*64, Tk_, Tv_, maskS,
                         qv, ktile, vtile, pbuf, keepm, fac, l_sh, oacc);

    for (int i = t; i < 64*64; i += 512) {
        const int qq = i >> 6, d = i & 63;
        dstPart[((size_t)(b_*1024 + q0 + qq))*1024 + (head & 15)*64 + d] = oacc[qq*68 + d];
    }
}

// ---------------- Kernel 5: merge partials ----------------
__global__ void __launch_bounds__(256) k_merge(float* __restrict__ out) {
    const size_t i = ((size_t)blockIdx.x * 256 + threadIdx.x) * 4;
    float4 a = *(const float4*)(g_pb + i);
    float4 b = *(const float4*)(g_pc + i);
    float4 o;
    o.x = a.x + b.x; o.y = a.y + b.y; o.z = a.z + b.z; o.w = a.w + b.w;
    *(float4*)(out + i) = o;
}

// ---------------- host ----------------
extern "C" void kernel_launch(void* const* d_in, const int* in_sizes, int n_in,
                              void* d_out, int out_size) {
    const float* x  = (const float*)d_in[0];
    const float* am = (const float*)d_in[1];
    const float* Wq = (const float*)d_in[2]; const float* bq = (const float*)d_in[3];
    const float* Wk = (const float*)d_in[4]; const float* bk = (const float*)d_in[5];
    const float* Wv = (const float*)d_in[6]; const float* bv = (const float*)d_in[7];
    const float* A[8]; const float* Bm[8];
    for (int i = 0; i < 8; i++) { A[i] = (const float*)d_in[8 + 2*i]; Bm[i] = (const float*)d_in[9 + 2*i]; }
    float* out = (float*)d_out;

    cudaFuncSetAttribute(k_attA, cudaFuncAttributeMaxDynamicSharedMemorySize, A_SMEM_BYTES);
    cudaFuncSetAttribute(k_attBC, cudaFuncAttributeMaxDynamicSharedMemorySize, BC_SMEM_BYTES);

    k_base_gemm<<<dim3(8, 16, 3), 256>>>(x, Wq, bq, Wk, bk, Wv, bv);
    k_xa_gemm<<<dim3(32, 8), 256>>>(x, A[0],A[1],A[2],A[3],A[4],A[5],A[6],A[7]);
    k_expand<<<dim3(16, 32, 8), 256>>>(Bm[0],Bm[1],Bm[2],Bm[3],Bm[4],Bm[5],Bm[6],Bm[7]);
    k_attA<<<dim3(16, 32), 512, A_SMEM_BYTES>>>(am);
    k_attBC<<<dim3(16, 32, 2), 512, BC_SMEM_BYTES>>>(am);
    k_merge<<<2048, 256>>>(out);
}

// round 14
// speedup vs baseline: 1.1734x; 1.0149x over previous
#include <cuda_runtime.h>
#include <cstdint>

// B=2, S=1024, H=1024, NH=16, HD=64, R=32, TOPK=128
#define TOPK 128

// device scratch (no allocation allowed)
__device__ __align__(16) float g_t[3u * 2048u * 1024u];         // tq,tk,tv
__device__ __align__(16) float g_xa[2048u * 256u];              // x @ [A0..A7]
__device__ __align__(16) float g_heads[8u * 32u * 1024u * 64u]; // [br][b*16+h][s][d]
__device__ __align__(16) unsigned g_keep[32u * 16u * 64u * 32u]; // [head][qt][q][word]
__device__ __align__(16) float g_pb[2048u * 1024u];             // est-branch partial
__device__ __align__(16) float g_pc[2048u * 1024u];             // sparse-branch partial

// ---- Kernel 1: t_z = x @ W_z + b_z (two-level FFMA, double-buffered) ------
__global__ void __launch_bounds__(256) k_base_gemm(
    const float* __restrict__ x,
    const float* __restrict__ W0, const float* __restrict__ b0,
    const float* __restrict__ W1, const float* __restrict__ b1,
    const float* __restrict__ W2, const float* __restrict__ b2)
{
    const int z = blockIdx.z;
    const float* W    = (z == 0) ? W0 : ((z == 1) ? W1 : W2);
    const float* bias = (z == 0) ? b0 : ((z == 1) ? b1 : b2);
    float* C = g_t + (size_t)z * 2048u * 1024u;

    const int m0 = blockIdx.y * 128, n0 = blockIdx.x * 128;
    __shared__ __align__(16) float As[2][16][128];
    __shared__ __align__(16) float Bs[2][16][128];

    const int t = threadIdx.x, ty = t >> 4, tx = t & 15;
    float acc[8][8], part[8][8];
#pragma unroll
    for (int i = 0; i < 8; i++)
#pragma unroll
        for (int j = 0; j < 8; j++) { acc[i][j] = 0.f; part[i][j] = 0.f; }

    const int am = t >> 1, ak = (t & 1) * 8;
    const int bk = t >> 4, bn = (t & 15) * 8;

    {   // preload tile 0 into buffer 0
        float4 a0 = *(const float4*)(x + (size_t)(m0 + am) * 1024 + ak);
        float4 a1 = *(const float4*)(x + (size_t)(m0 + am) * 1024 + ak + 4);
        float4 w0 = *(const float4*)(W + (size_t)bk * 1024 + n0 + bn);
        float4 w1 = *(const float4*)(W + (size_t)bk * 1024 + n0 + bn + 4);
        As[0][ak + 0][am] = a0.x; As[0][ak + 1][am] = a0.y; As[0][ak + 2][am] = a0.z; As[0][ak + 3][am] = a0.w;
        As[0][ak + 4][am] = a1.x; As[0][ak + 5][am] = a1.y; As[0][ak + 6][am] = a1.z; As[0][ak + 7][am] = a1.w;
        *(float4*)&Bs[0][bk][bn] = w0;  *(float4*)&Bs[0][bk][bn + 4] = w1;
    }
    __syncthreads();

#pragma unroll 1
    for (int kt = 0; kt < 64; kt++) {
        const int cur = kt & 1, nxt = cur ^ 1;
        float4 a0n, a1n, w0n, w1n;
        if (kt < 63) {
            const int k0 = (kt + 1) * 16;
            a0n = *(const float4*)(x + (size_t)(m0 + am) * 1024 + k0 + ak);
            a1n = *(const float4*)(x + (size_t)(m0 + am) * 1024 + k0 + ak + 4);
            w0n = *(const float4*)(W + (size_t)(k0 + bk) * 1024 + n0 + bn);
            w1n = *(const float4*)(W + (size_t)(k0 + bk) * 1024 + n0 + bn + 4);
        }
#pragma unroll
        for (int kk = 0; kk < 16; kk++) {
            float a[8], b[8];
            *(float4*)&a[0] = *(const float4*)&As[cur][kk][ty * 8];
            *(float4*)&a[4] = *(const float4*)&As[cur][kk][ty * 8 + 4];
            *(float4*)&b[0] = *(const float4*)&Bs[cur][kk][tx * 8];
            *(float4*)&b[4] = *(const float4*)&Bs[cur][kk][tx * 8 + 4];
#pragma unroll
            for (int i = 0; i < 8; i++)
#pragma unroll
                for (int j = 0; j < 8; j++) part[i][j] += a[i] * b[j];
        }
        if (kt < 63) {
            As[nxt][ak + 0][am] = a0n.x; As[nxt][ak + 1][am] = a0n.y;
            As[nxt][ak + 2][am] = a0n.z; As[nxt][ak + 3][am] = a0n.w;
            As[nxt][ak + 4][am] = a1n.x; As[nxt][ak + 5][am] = a1n.y;
            As[nxt][ak + 6][am] = a1n.z; As[nxt][ak + 7][am] = a1n.w;
            *(float4*)&Bs[nxt][bk][bn] = w0n;  *(float4*)&Bs[nxt][bk][bn + 4] = w1n;
        }
        if ((kt & 3) == 3) {
#pragma unroll
            for (int i = 0; i < 8; i++)
#pragma unroll
                for (int j = 0; j < 8; j++) { acc[i][j] += part[i][j]; part[i][j] = 0.f; }
        }
        __syncthreads();
    }
#pragma unroll
    for (int i = 0; i < 8; i++) {
        const int row = m0 + ty * 8 + i;
#pragma unroll
        for (int j4 = 0; j4 < 2; j4++) {
            const int col = n0 + tx * 8 + j4 * 4;
            float4 bb = *(const float4*)(bias + col);
            float4 o;
            o.x = acc[i][j4*4+0] + bb.x; o.y = acc[i][j4*4+1] + bb.y;
            o.z = acc[i][j4*4+2] + bb.z; o.w = acc[i][j4*4+3] + bb.w;
            *(float4*)(C + (size_t)row * 1024 + col) = o;
        }
    }
}

// -------- Kernel 2: xa = x @ A_br (double-buffered) --------
__global__ void __launch_bounds__(256) k_xa_gemm(
    const float* __restrict__ x,
    const float* A0, const float* A1, const float* A2, const float* A3,
    const float* A4, const float* A5, const float* A6, const float* A7)
{
    const int br = blockIdx.y;
    const float* A;
    switch (br) { case 0: A=A0; break; case 1: A=A1; break; case 2: A=A2; break; case 3: A=A3; break;
                  case 4: A=A4; break; case 5: A=A5; break; case 6: A=A6; break; default: A=A7; }
    const int m0 = blockIdx.x * 64;
    __shared__ float xs[2][32][64];
    __shared__ __align__(16) float as_[2][32][32];

    const int t = threadIdx.x;
    const int mm = t >> 2, rb = (t & 3) * 8;
    const int lm = t >> 2, lk = (t & 3) * 8;
    const int akk = t >> 3, ar = (t & 7) * 4;

    float acc[8];
#pragma unroll
    for (int j = 0; j < 8; j++) acc[j] = 0.f;

    {   // preload tile 0
        float4 x0 = *(const float4*)(x + (size_t)(m0 + lm) * 1024 + lk);
        float4 x1 = *(const float4*)(x + (size_t)(m0 + lm) * 1024 + lk + 4);
        float4 a4 = *(const float4*)(A + (size_t)akk * 32 + ar);
        xs[0][lk+0][lm]=x0.x; xs[0][lk+1][lm]=x0.y; xs[0][lk+2][lm]=x0.z; xs[0][lk+3][lm]=x0.w;
        xs[0][lk+4][lm]=x1.x; xs[0][lk+5][lm]=x1.y; xs[0][lk+6][lm]=x1.z; xs[0][lk+7][lm]=x1.w;
        *(float4*)&as_[0][akk][ar] = a4;
    }
    __syncthreads();

#pragma unroll 1
    for (int kt = 0; kt < 32; kt++) {
        const int cur = kt & 1, nxt = cur ^ 1;
        float4 x0n, x1n, a4n;
        if (kt < 31) {
            const int k0 = (kt + 1) * 32;
            x0n = *(const float4*)(x + (size_t)(m0 + lm) * 1024 + k0 + lk);
            x1n = *(const float4*)(x + (size_t)(m0 + lm) * 1024 + k0 + lk + 4);
            a4n = *(const float4*)(A + (size_t)(k0 + akk) * 32 + ar);
        }
        float part[8];
#pragma unroll
        for (int j = 0; j < 8; j++) part[j] = 0.f;
#pragma unroll
        for (int kk = 0; kk < 32; kk++) {
            const float xv = xs[cur][kk][mm];
#pragma unroll
            for (int j = 0; j < 8; j++) part[j] += xv * as_[cur][kk][rb + j];
        }
#pragma unroll
        for (int j = 0; j < 8; j++) acc[j] += part[j];
        if (kt < 31) {
            xs[nxt][lk+0][lm]=x0n.x; xs[nxt][lk+1][lm]=x0n.y; xs[nxt][lk+2][lm]=x0n.z; xs[nxt][lk+3][lm]=x0n.w;
            xs[nxt][lk+4][lm]=x1n.x; xs[nxt][lk+5][lm]=x1n.y; xs[nxt][lk+6][lm]=x1n.z; xs[nxt][lk+7][lm]=x1n.w;
            *(float4*)&as_[nxt][akk][ar] = a4n;
        }
        __syncthreads();
    }
    *(float4*)(g_xa + (size_t)(m0+mm)*256 + br*32 + rb)   = make_float4(acc[0],acc[1],acc[2],acc[3]);
    *(float4*)(g_xa + (size_t)(m0+mm)*256 + br*32 + rb+4) = make_float4(acc[4],acc[5],acc[6],acc[7]);
}

// ------- Kernel 3: heads[br] = base(br) + xa_br @ B_br, head layout -------
__global__ void __launch_bounds__(256) k_expand(
    const float* B0, const float* B1, const float* B2, const float* B3,
    const float* B4, const float* B5, const float* B6, const float* B7)
{
    const int br = blockIdx.z;
    const float* Bm;
    switch (br) { case 0: Bm=B0; break; case 1: Bm=B1; break; case 2: Bm=B2; break; case 3: Bm=B3; break;
                  case 4: Bm=B4; break; case 5: Bm=B5; break; case 6: Bm=B6; break; default: Bm=B7; }
    const int baseIdx = (br == 2 || br == 7) ? 2 : ((br == 1 || br == 4 || br == 6) ? 1 : 0);
    const float* tb = g_t + (size_t)baseIdx * 2048u * 1024u;

    const int m0 = blockIdx.y * 64, n0 = blockIdx.x * 64;
    __shared__ __align__(16) float xaS[32][68];
    __shared__ __align__(16) float bS[32][68];

    const int t = threadIdx.x;
    {
        const int m = t >> 2, rr = (t & 3) * 8;
        float4 v0 = *(const float4*)(g_xa + (size_t)(m0+m)*256 + br*32 + rr);
        float4 v1 = *(const float4*)(g_xa + (size_t)(m0+m)*256 + br*32 + rr + 4);
        xaS[rr+0][m]=v0.x; xaS[rr+1][m]=v0.y; xaS[rr+2][m]=v0.z; xaS[rr+3][m]=v0.w;
        xaS[rr+4][m]=v1.x; xaS[rr+5][m]=v1.y; xaS[rr+6][m]=v1.z; xaS[rr+7][m]=v1.w;
    }
    {
        const int r = t >> 3, nn = (t & 7) * 8;
        *(float4*)&bS[r][nn]   = *(const float4*)(Bm + (size_t)r*1024 + n0 + nn);
        *(float4*)&bS[r][nn+4] = *(const float4*)(Bm + (size_t)r*1024 + n0 + nn + 4);
    }
    __syncthreads();

    const int ty = t >> 4, tx = t & 15;
    float acc[4][4];
#pragma unroll
    for (int i = 0; i < 4; i++)
#pragma unroll
        for (int j = 0; j < 4; j++) acc[i][j] = 0.f;
#pragma unroll
    for (int r = 0; r < 32; r++) {
        float4 a4 = *(const float4*)&xaS[r][ty*4];
        float4 b4 = *(const float4*)&bS[r][tx*4];
        acc[0][0]+=a4.x*b4.x; acc[0][1]+=a4.x*b4.y; acc[0][2]+=a4.x*b4.z; acc[0][3]+=a4.x*b4.w;
        acc[1][0]+=a4.y*b4.x; acc[1][1]+=a4.y*b4.y; acc[1][2]+=a4.y*b4.z; acc[1][3]+=a4.y*b4.w;
        acc[2][0]+=a4.z*b4.x; acc[2][1]+=a4.z*b4.y; acc[2][2]+=a4.z*b4.z; acc[2][3]+=a4.z*b4.w;
        acc[3][0]+=a4.w*b4.x; acc[3][1]+=a4.w*b4.y; acc[3][2]+=a4.w*b4.z; acc[3][3]+=a4.w*b4.w;
    }

    const int h = blockIdx.x;
#pragma unroll
    for (int i = 0; i < 4; i++) {
        const int m = m0 + ty*4 + i, b_ = m >> 10, s = m & 1023;
        float4 base = *(const float4*)(tb + (size_t)m*1024 + n0 + tx*4);
        float4 o;
        o.x=acc[i][0]+base.x; o.y=acc[i][1]+base.y; o.z=acc[i][2]+base.z; o.w=acc[i][3]+base.w;
        *(float4*)(g_heads + (((size_t)br*32 + b_*16 + h)*1024 + s)*64 + tx*4) = o;
    }
}

// ---------------- attention helpers ----------------
__device__ __forceinline__ unsigned fmap(float f) {
    unsigned u = __float_as_uint(f);
    return (u & 0x80000000u) ? ~u : (u | 0x80000000u);
}
__device__ __forceinline__ float wredmax(float v) {
#pragma unroll
    for (int o = 16; o > 0; o >>= 1) v = fmaxf(v, __shfl_xor_sync(0xffffffffu, v, o));
    return v;
}
__device__ __forceinline__ float wredsum(float v) {
#pragma unroll
    for (int o = 16; o > 0; o >>= 1) v += __shfl_xor_sync(0xffffffffu, v, o);
    return v;
}

// ---------------- Kernel 4a: phase A (top-k keep bitmask) ----------------
#define A_OFF_KT   0
#define A_OFF_VT   8704
#define A_OFF_QV   (2*8704)
#define A_OFF_MASK (A_OFF_QV + 64*68)
#define A_SMEM_BYTES ((A_OFF_MASK + 1024) * 4)   // 91,136 B

__global__ void __launch_bounds__(512) k_attA(const float* __restrict__ am)
{
    extern __shared__ float smf[];
    float* ktile = smf + A_OFF_KT;
    float* vtile = smf + A_OFF_VT;
    float* qv    = smf + A_OFF_QV;
    float* maskS = smf + A_OFF_MASK;

    const int t = threadIdx.x;
    const int head = blockIdx.y;
    const int qt = blockIdx.x;
    const int q0 = qt * 64;
    const int b_ = head >> 4;

    for (int i = t; i < 1024; i += 512) maskS[i] = am[b_*1024 + i];

    const size_t hs = (size_t)1024 * 64;
    const float* Tqs = g_heads + (3u*32 + head)*hs;
    const float* Tks = g_heads + (4u*32 + head)*hs;

    {   // load 64 qs rows
        const int q = t >> 3, d = (t & 7) * 8;
        *(float4*)&qv[q*68 + d]     = *(const float4*)(Tqs + (size_t)(q0 + q)*64 + d);
        *(float4*)&qv[q*68 + d + 4] = *(const float4*)(Tqs + (size_t)(q0 + q)*64 + d + 4);
    }
    __syncthreads();

    const int qp = t >> 5, kb = t & 31;
    unsigned* gk = g_keep + (((size_t)head*16 + qt)*64)*32;
#pragma unroll 1
    for (int pass = 0; pass < 2; pass++) {
        const int qA = pass*32 + 2*qp, qB = qA + 1;
        unsigned uv0[32], uv1[32];

        {   // prologue: tile 0 -> ktile
            const int kloc = t >> 2, dd = (t & 3) * 16;
            const float* src = Tks + (size_t)kloc*64 + dd;
            float* dst = ktile + kloc*68 + dd;
#pragma unroll
            for (int jj = 0; jj < 4; jj++) *(float4*)(dst + jj*4) = *(const float4*)(src + jj*4);
        }
        __syncthreads();

        // FULLY UNROLLED tile loop: static uv indices -> registers (no local spill)
#pragma unroll
        for (int kt = 0; kt < 8; kt++) {
            float* cur = (kt & 1) ? vtile : ktile;
            float* nxt = (kt & 1) ? ktile : vtile;
            if (kt < 7) {
                const int kloc = t >> 2, dd = (t & 3) * 16;
                const float* src = Tks + ((size_t)(kt+1)*128 + kloc)*64 + dd;
                float* dst = nxt + kloc*68 + dd;
#pragma unroll
                for (int jj = 0; jj < 4; jj++) *(float4*)(dst + jj*4) = *(const float4*)(src + jj*4);
            }
            float s0[4] = {0.f,0.f,0.f,0.f}, s1[4] = {0.f,0.f,0.f,0.f};
            const float4* q0v = (const float4*)(qv + qA*68);
            const float4* q1v = (const float4*)(qv + qB*68);
#pragma unroll
            for (int d4 = 0; d4 < 16; d4++) {
                const float4 f0 = q0v[d4], f1 = q1v[d4];
#pragma unroll
                for (int j = 0; j < 4; j++) {
                    const float4 kf = *(const float4*)(cur + (kb + 32*j)*68 + d4*4);
                    s0[j] += f0.x*kf.x + f0.y*kf.y + f0.z*kf.z + f0.w*kf.w;
                    s1[j] += f1.x*kf.x + f1.y*kf.y + f1.z*kf.z + f1.w*kf.w;
                }
            }
#pragma unroll
            for (int j = 0; j < 4; j++) {
                const float mv = maskS[kt*128 + 32*j + kb];
                uv0[kt*4+j] = fmap(s0[j] * 0.125f + mv);
                uv1[kt*4+j] = fmap(s1[j] * 0.125f + mv);
            }
            __syncthreads();
        }

        // dual exact kth-largest binary search; single REDUX per iteration
        unsigned lo0 = 0u, hi0 = 0xFFFFFFFFu, lo1 = 0u, hi1 = 0xFFFFFFFFu;
#pragma unroll 1
        for (int it = 0; it < 32; it++) {
            const unsigned d0 = hi0 - lo0, d1 = hi1 - lo1;
            const unsigned mid0 = lo0 + (d0 >> 1) + (d0 & 1u);
            const unsigned mid1 = lo1 + (d1 >> 1) + (d1 & 1u);
            unsigned c0 = 0, c1 = 0;
#pragma unroll
            for (int i = 0; i < 32; i++) {
                c0 += (uv0[i] >= mid0) ? 1u : 0u;
                c1 += (uv1[i] >= mid1) ? 1u : 0u;
            }
            const unsigned packed = __reduce_add_sync(0xffffffffu, c0 | (c1 << 16));
            const unsigned t0 = packed & 0xFFFFu, t1 = packed >> 16;
            if (t0 >= TOPK) lo0 = mid0; else hi0 = mid0 - 1u;
            if (t1 >= TOPK) lo1 = mid1; else hi1 = mid1 - 1u;
        }
#pragma unroll
        for (int i = 0; i < 32; i++) {
            const unsigned b0 = __ballot_sync(0xffffffffu, uv0[i] >= lo0);
            const unsigned b1 = __ballot_sync(0xffffffffu, uv1[i] >= lo1);
            if (kb == 0) { gk[qA*32 + i] = b0; gk[qB*32 + i] = b1; }
        }
        __syncthreads();
    }
}

// ---------------- Kernel 4b: phases B/C (z selects branch) ----------------
#define OFF_KT   0
#define OFF_VT   8704
#define OFF_QV   (2*8704)
#define OFF_MASK (OFF_QV + 64*68)
#define OFF_PBUF (OFF_MASK + 1024)
#define OFF_OA   (OFF_PBUF + 64*128)
#define OFF_FAC  (OFF_OA + 64*68)
#define OFF_LSH  (OFF_FAC + 64)
#define OFF_KEEP (OFF_LSH + 64)
#define BC_SMEM_BYTES ((OFF_KEEP + 64*32) * 4)   // 150,016 B

template<bool KEEP>
__device__ void attn_phase(
    const int t,
    const float* __restrict__ qptr, const float* __restrict__ kptr,
    const float* __restrict__ vptr, const float* __restrict__ maskS,
    float* qv, float* ktile, float* vtile, float* pbuf,
    const unsigned* __restrict__ keepm, float* fac, float* l_sh, float* oacc)
{
    {
        const int q = t >> 3, d = (t & 7) * 8;
        *(float4*)&qv[q*68 + d]     = *(const float4*)(qptr + (size_t)q*64 + d);
        *(float4*)&qv[q*68 + d + 4] = *(const float4*)(qptr + (size_t)q*64 + d + 4);
    }
    for (int i = t; i < 64*68; i += 512) oacc[i] = 0.f;

    float o[8][4];
#pragma unroll
    for (int i = 0; i < 8; i++)
#pragma unroll
        for (int j = 0; j < 4; j++) o[i][j] = 0.f;

    const int w  = t >> 5;
    const int kb = t & 31;
    const int dg = t & 15, kg = (t >> 4) & 3, qg = t >> 6;
    float m_[4], l_[4];
#pragma unroll
    for (int qi = 0; qi < 4; qi++) { m_[qi] = -1e30f; l_[qi] = 0.f; }
    __syncthreads();

    for (int kt = 0; kt < 8; kt++) {
        {
            const int kloc = t >> 2, dd = (t & 3) * 16;
            const float* ksrc = kptr + ((size_t)kt*128 + kloc)*64 + dd;
            const float* vsrc = vptr + ((size_t)kt*128 + kloc)*64 + dd;
            float4 kr[4], vr[4];
#pragma unroll
            for (int jj = 0; jj < 4; jj++) kr[jj] = *(const float4*)(ksrc + jj*4);
#pragma unroll
            for (int jj = 0; jj < 4; jj++) vr[jj] = *(const float4*)(vsrc + jj*4);
            float* kdst = ktile + kloc*68 + dd;
            float* vdst = vtile + kloc*68 + dd;
#pragma unroll
            for (int jj = 0; jj < 4; jj++) *(float4*)(kdst + jj*4) = kr[jj];
#pragma unroll
            for (int jj = 0; jj < 4; jj++) *(float4*)(vdst + jj*4) = vr[jj];
        }
        __syncthreads();

        float s[4][4];
#pragma unroll
        for (int qi = 0; qi < 4; qi++)
#pragma unroll
            for (int j = 0; j < 4; j++) s[qi][j] = 0.f;
#pragma unroll
        for (int d4 = 0; d4 < 16; d4++) {
            float4 qf[4];
#pragma unroll
            for (int qi = 0; qi < 4; qi++)
                qf[qi] = *(const float4*)(qv + (4*w + qi)*68 + d4*4);
#pragma unroll
            for (int j = 0; j < 4; j++) {
                const float4 kf = *(const float4*)(ktile + (kb + 32*j)*68 + d4*4);
#pragma unroll
                for (int qi = 0; qi < 4; qi++)
                    s[qi][j] += qf[qi].x*kf.x + qf[qi].y*kf.y + qf[qi].z*kf.z + qf[qi].w*kf.w;
            }
        }
#pragma unroll
        for (int qi = 0; qi < 4; qi++) {
            bool kp[4];
            float tmx = -1e30f;
#pragma unroll
            for (int j = 0; j < 4; j++) {
                const int key = kt*128 + 32*j + kb;
                float sv = s[qi][j] * 0.125f + maskS[key];
                if (KEEP) {
                    kp[j] = (keepm[(4*w + qi)*32 + kt*4 + j] >> kb) & 1u;
                    if (!kp[j]) sv = -1e30f;
                } else kp[j] = true;
                s[qi][j] = sv;
                tmx = fmaxf(tmx, sv);
            }
            tmx = wredmax(tmx);
            const float nm = fmaxf(m_[qi], tmx);
            const float fr = __expf(m_[qi] - nm);
            m_[qi] = nm;
            if (kb == 0) fac[4*w + qi] = fr;
            float ps = 0.f;
#pragma unroll
            for (int j = 0; j < 4; j++) {
                float p = __expf(s[qi][j] - nm);
                if (KEEP && !kp[j]) p = 0.f;
                pbuf[(4*w + qi)*128 + 32*j + kb] = p;
                ps += p;
            }
            ps = wredsum(ps);
            l_[qi] = l_[qi] * fr + ps;
        }
        __syncthreads();

        {
            float fq[8];
#pragma unroll
            for (int qi = 0; qi < 8; qi++) fq[qi] = fac[8*qg + qi];
#pragma unroll
            for (int qi = 0; qi < 8; qi++) {
                o[qi][0]*=fq[qi]; o[qi][1]*=fq[qi]; o[qi][2]*=fq[qi]; o[qi][3]*=fq[qi];
            }
#pragma unroll
            for (int kk4 = 0; kk4 < 8; kk4++) {
                const int base2 = kg*32 + kk4*4;
                const float4 v0 = *(const float4*)(vtile + (base2+0)*68 + dg*4);
                const float4 v1 = *(const float4*)(vtile + (base2+1)*68 + dg*4);
                const float4 v2 = *(const float4*)(vtile + (base2+2)*68 + dg*4);
                const float4 v3 = *(const float4*)(vtile + (base2+3)*68 + dg*4);
#pragma unroll
                for (int qi = 0; qi < 8; qi++) {
                    const float4 p4 = *(const float4*)(pbuf + (8*qg + qi)*128 + base2);
                    o[qi][0] += p4.x*v0.x + p4.y*v1.x + p4.z*v2.x + p4.w*v3.x;
                    o[qi][1] += p4.x*v0.y + p4.y*v1.y + p4.z*v2.y + p4.w*v3.y;
                    o[qi][2] += p4.x*v0.z + p4.y*v1.z + p4.z*v2.z + p4.w*v3.z;
                    o[qi][3] += p4.x*v0.w + p4.y*v1.w + p4.z*v2.w + p4.w*v3.w;
                }
            }
        }
        __syncthreads();
    }

    if (kb == 0) {
#pragma unroll
        for (int qi = 0; qi < 4; qi++) l_sh[4*w + qi] = l_[qi];
    }
    for (int turn = 0; turn < 4; turn++) {
        if (kg == turn) {
#pragma unroll
            for (int qi = 0; qi < 8; qi++) {
                float* dst = oacc + (8*qg + qi)*68 + dg*4;
                dst[0]+=o[qi][0]; dst[1]+=o[qi][1]; dst[2]+=o[qi][2]; dst[3]+=o[qi][3];
            }
        }
        __syncthreads();
    }
    for (int i = t; i < 64*64; i += 512) {
        const int qq = i >> 6, d = i & 63;
        oacc[qq*68 + d] *= 0.5f / l_sh[qq];
    }
    __syncthreads();
}

__global__ void __launch_bounds__(512) k_attBC(const float* __restrict__ am)
{
    extern __shared__ float smf[];
    float* ktile = smf + OFF_KT;
    float* vtile = smf + OFF_VT;
    float* qv    = smf + OFF_QV;
    float* maskS = smf + OFF_MASK;
    float* pbuf  = smf + OFF_PBUF;
    float* oacc  = smf + OFF_OA;
    float* fac   = smf + OFF_FAC;
    float* l_sh  = smf + OFF_LSH;
    unsigned* keepm = (unsigned*)(smf + OFF_KEEP);

    const int t = threadIdx.x;
    const int head = blockIdx.y;
    const int qt = blockIdx.x;
    const int q0 = qt * 64;
    const int b_ = head >> 4;
    const int z = blockIdx.z;       // 0 = est branch, 1 = sparse branch

    for (int i = t; i < 1024; i += 512) maskS[i] = am[b_*1024 + i];

    const size_t hs = (size_t)1024 * 64;
    const float *Tq_, *Tk_, *Tv_;
    float* dstPart;
    if (z == 0) {
        Tq_ = g_heads + (5u*32 + head)*hs;  // qa
        Tk_ = g_heads + (6u*32 + head)*hs;  // ka
        Tv_ = g_heads + (7u*32 + head)*hs;  // va
        dstPart = g_pb;
    } else {
        Tq_ = g_heads + (0u*32 + head)*hs;  // q
        Tk_ = g_heads + (1u*32 + head)*hs;  // k
        Tv_ = g_heads + (2u*32 + head)*hs;  // v
        dstPart = g_pc;
        const unsigned* gk = g_keep + (((size_t)head*16 + qt)*64)*32;
        for (int i = t; i < 64*32; i += 512) keepm[i] = gk[i];
    }
    __syncthreads();

    if (z == 0)
        attn_phase<false>(t, Tq_ + (size_t)q0*64, Tk_, Tv_, maskS,
                          qv, ktile, vtile, pbuf, keepm, fac, l_sh, oacc);
    else
        attn_phase<true>(t, Tq_ + (size_t)q0*64, Tk_, Tv_, maskS,
                         qv, ktile, vtile, pbuf, keepm, fac, l_sh, oacc);

    for (int i = t; i < 64*64; i += 512) {
        const int qq = i >> 6, d = i & 63;
        dstPart[((size_t)(b_*1024 + q0 + qq))*1024 + (head & 15)*64 + d] = oacc[qq*68 + d];
    }
}

// ---------------- Kernel 5: merge partials ----------------
__global__ void __launch_bounds__(256) k_merge(float* __restrict__ out) {
    const size_t i = ((size_t)blockIdx.x * 256 + threadIdx.x) * 4;
    float4 a = *(const float4*)(g_pb + i);
    float4 b = *(const float4*)(g_pc + i);
    float4 o;
    o.x = a.x + b.x; o.y = a.y + b.y; o.z = a.z + b.z; o.w = a.w + b.w;
    *(float4*)(out + i) = o;
}

// ---------------- host ----------------
extern "C" void kernel_launch(void* const* d_in, const int* in_sizes, int n_in,
                              void* d_out, int out_size) {
    const float* x  = (const float*)d_in[0];
    const float* am = (const float*)d_in[1];
    const float* Wq = (const float*)d_in[2]; const float* bq = (const float*)d_in[3];
    const float* Wk = (const float*)d_in[4]; const float* bk = (const float*)d_in[5];
    const float* Wv = (const float*)d_in[6]; const float* bv = (const float*)d_in[7];
    const float* A[8]; const float* Bm[8];
    for (int i = 0; i < 8; i++) { A[i] = (const float*)d_in[8 + 2*i]; Bm[i] = (const float*)d_in[9 + 2*i]; }
    float* out = (float*)d_out;

    cudaFuncSetAttribute(k_attA, cudaFuncAttributeMaxDynamicSharedMemorySize, A_SMEM_BYTES);
    cudaFuncSetAttribute(k_attBC, cudaFuncAttributeMaxDynamicSharedMemorySize, BC_SMEM_BYTES);

    k_base_gemm<<<dim3(8, 16, 3), 256>>>(x, Wq, bq, Wk, bk, Wv, bv);
    k_xa_gemm<<<dim3(32, 8), 256>>>(x, A[0],A[1],A[2],A[3],A[4],A[5],A[6],A[7]);
    k_expand<<<dim3(16, 32, 8), 256>>>(Bm[0],Bm[1],Bm[2],Bm[3],Bm[4],Bm[5],Bm[6],Bm[7]);
    k_attA<<<dim3(16, 32), 512, A_SMEM_BYTES>>>(am);
    k_attBC<<<dim3(16, 32, 2), 512, BC_SMEM_BYTES>>>(am);
    k_merge<<<2048, 256>>>(out);
}

// round 15
// speedup vs baseline: 1.2515x; 1.0666x over previous
#include <cuda_runtime.h>
#include <cstdint>

// B=2, S=1024, H=1024, NH=16, HD=64, R=32, TOPK=128
#define TOPK 128

// device scratch (no allocation allowed)
__device__ __align__(16) float g_t[3u * 2048u * 1024u];         // tq,tk,tv
__device__ __align__(16) float g_xa[2048u * 256u];              // x @ [A0..A7]
__device__ __align__(16) float g_heads[8u * 32u * 1024u * 64u]; // [br][b*16+h][s][d]
__device__ __align__(16) unsigned g_keep[32u * 16u * 64u * 32u]; // [head][qt][q][word]
__device__ __align__(16) float g_pb[2048u * 1024u];             // est-branch partial
__device__ __align__(16) float g_pc[2048u * 1024u];             // sparse-branch partial

// ---- Kernel 1: t_z = x @ W_z + b_z (two-level FFMA, double-buffered) ------
__global__ void __launch_bounds__(256) k_base_gemm(
    const float* __restrict__ x,
    const float* __restrict__ W0, const float* __restrict__ b0,
    const float* __restrict__ W1, const float* __restrict__ b1,
    const float* __restrict__ W2, const float* __restrict__ b2)
{
    const int z = blockIdx.z;
    const float* W    = (z == 0) ? W0 : ((z == 1) ? W1 : W2);
    const float* bias = (z == 0) ? b0 : ((z == 1) ? b1 : b2);
    float* C = g_t + (size_t)z * 2048u * 1024u;

    const int m0 = blockIdx.y * 128, n0 = blockIdx.x * 128;
    __shared__ __align__(16) float As[2][16][128];
    __shared__ __align__(16) float Bs[2][16][128];

    const int t = threadIdx.x, ty = t >> 4, tx = t & 15;
    float acc[8][8], part[8][8];
#pragma unroll
    for (int i = 0; i < 8; i++)
#pragma unroll
        for (int j = 0; j < 8; j++) { acc[i][j] = 0.f; part[i][j] = 0.f; }

    const int am = t >> 1, ak = (t & 1) * 8;
    const int bk = t >> 4, bn = (t & 15) * 8;

    {   // preload tile 0 into buffer 0
        float4 a0 = *(const float4*)(x + (size_t)(m0 + am) * 1024 + ak);
        float4 a1 = *(const float4*)(x + (size_t)(m0 + am) * 1024 + ak + 4);
        float4 w0 = *(const float4*)(W + (size_t)bk * 1024 + n0 + bn);
        float4 w1 = *(const float4*)(W + (size_t)bk * 1024 + n0 + bn + 4);
        As[0][ak + 0][am] = a0.x; As[0][ak + 1][am] = a0.y; As[0][ak + 2][am] = a0.z; As[0][ak + 3][am] = a0.w;
        As[0][ak + 4][am] = a1.x; As[0][ak + 5][am] = a1.y; As[0][ak + 6][am] = a1.z; As[0][ak + 7][am] = a1.w;
        *(float4*)&Bs[0][bk][bn] = w0;  *(float4*)&Bs[0][bk][bn + 4] = w1;
    }
    __syncthreads();

#pragma unroll 1
    for (int kt = 0; kt < 64; kt++) {
        const int cur = kt & 1, nxt = cur ^ 1;
        float4 a0n, a1n, w0n, w1n;
        if (kt < 63) {
            const int k0 = (kt + 1) * 16;
            a0n = *(const float4*)(x + (size_t)(m0 + am) * 1024 + k0 + ak);
            a1n = *(const float4*)(x + (size_t)(m0 + am) * 1024 + k0 + ak + 4);
            w0n = *(const float4*)(W + (size_t)(k0 + bk) * 1024 + n0 + bn);
            w1n = *(const float4*)(W + (size_t)(k0 + bk) * 1024 + n0 + bn + 4);
        }
#pragma unroll
        for (int kk = 0; kk < 16; kk++) {
            float a[8], b[8];
            *(float4*)&a[0] = *(const float4*)&As[cur][kk][ty * 8];
            *(float4*)&a[4] = *(const float4*)&As[cur][kk][ty * 8 + 4];
            *(float4*)&b[0] = *(const float4*)&Bs[cur][kk][tx * 8];
            *(float4*)&b[4] = *(const float4*)&Bs[cur][kk][tx * 8 + 4];
#pragma unroll
            for (int i = 0; i < 8; i++)
#pragma unroll
                for (int j = 0; j < 8; j++) part[i][j] += a[i] * b[j];
        }
        if (kt < 63) {
            As[nxt][ak + 0][am] = a0n.x; As[nxt][ak + 1][am] = a0n.y;
            As[nxt][ak + 2][am] = a0n.z; As[nxt][ak + 3][am] = a0n.w;
            As[nxt][ak + 4][am] = a1n.x; As[nxt][ak + 5][am] = a1n.y;
            As[nxt][ak + 6][am] = a1n.z; As[nxt][ak + 7][am] = a1n.w;
            *(float4*)&Bs[nxt][bk][bn] = w0n;  *(float4*)&Bs[nxt][bk][bn + 4] = w1n;
        }
        if ((kt & 3) == 3) {
#pragma unroll
            for (int i = 0; i < 8; i++)
#pragma unroll
                for (int j = 0; j < 8; j++) { acc[i][j] += part[i][j]; part[i][j] = 0.f; }
        }
        __syncthreads();
    }
#pragma unroll
    for (int i = 0; i < 8; i++) {
        const int row = m0 + ty * 8 + i;
#pragma unroll
        for (int j4 = 0; j4 < 2; j4++) {
            const int col = n0 + tx * 8 + j4 * 4;
            float4 bb = *(const float4*)(bias + col);
            float4 o;
            o.x = acc[i][j4*4+0] + bb.x; o.y = acc[i][j4*4+1] + bb.y;
            o.z = acc[i][j4*4+2] + bb.z; o.w = acc[i][j4*4+3] + bb.w;
            *(float4*)(C + (size_t)row * 1024 + col) = o;
        }
    }
}

// -------- Kernel 2: xa = x @ A_br (double-buffered) --------
__global__ void __launch_bounds__(256) k_xa_gemm(
    const float* __restrict__ x,
    const float* A0, const float* A1, const float* A2, const float* A3,
    const float* A4, const float* A5, const float* A6, const float* A7)
{
    const int br = blockIdx.y;
    const float* A;
    switch (br) { case 0: A=A0; break; case 1: A=A1; break; case 2: A=A2; break; case 3: A=A3; break;
                  case 4: A=A4; break; case 5: A=A5; break; case 6: A=A6; break; default: A=A7; }
    const int m0 = blockIdx.x * 64;
    __shared__ float xs[2][32][64];
    __shared__ __align__(16) float as_[2][32][32];

    const int t = threadIdx.x;
    const int mm = t >> 2, rb = (t & 3) * 8;
    const int lm = t >> 2, lk = (t & 3) * 8;
    const int akk = t >> 3, ar = (t & 7) * 4;

    float acc[8];
#pragma unroll
    for (int j = 0; j < 8; j++) acc[j] = 0.f;

    {   // preload tile 0
        float4 x0 = *(const float4*)(x + (size_t)(m0 + lm) * 1024 + lk);
        float4 x1 = *(const float4*)(x + (size_t)(m0 + lm) * 1024 + lk + 4);
        float4 a4 = *(const float4*)(A + (size_t)akk * 32 + ar);
        xs[0][lk+0][lm]=x0.x; xs[0][lk+1][lm]=x0.y; xs[0][lk+2][lm]=x0.z; xs[0][lk+3][lm]=x0.w;
        xs[0][lk+4][lm]=x1.x; xs[0][lk+5][lm]=x1.y; xs[0][lk+6][lm]=x1.z; xs[0][lk+7][lm]=x1.w;
        *(float4*)&as_[0][akk][ar] = a4;
    }
    __syncthreads();

#pragma unroll 1
    for (int kt = 0; kt < 32; kt++) {
        const int cur = kt & 1, nxt = cur ^ 1;
        float4 x0n, x1n, a4n;
        if (kt < 31) {
            const int k0 = (kt + 1) * 32;
            x0n = *(const float4*)(x + (size_t)(m0 + lm) * 1024 + k0 + lk);
            x1n = *(const float4*)(x + (size_t)(m0 + lm) * 1024 + k0 + lk + 4);
            a4n = *(const float4*)(A + (size_t)(k0 + akk) * 32 + ar);
        }
        float part[8];
#pragma unroll
        for (int j = 0; j < 8; j++) part[j] = 0.f;
#pragma unroll
        for (int kk = 0; kk < 32; kk++) {
            const float xv = xs[cur][kk][mm];
#pragma unroll
            for (int j = 0; j < 8; j++) part[j] += xv * as_[cur][kk][rb + j];
        }
#pragma unroll
        for (int j = 0; j < 8; j++) acc[j] += part[j];
        if (kt < 31) {
            xs[nxt][lk+0][lm]=x0n.x; xs[nxt][lk+1][lm]=x0n.y; xs[nxt][lk+2][lm]=x0n.z; xs[nxt][lk+3][lm]=x0n.w;
            xs[nxt][lk+4][lm]=x1n.x; xs[nxt][lk+5][lm]=x1n.y; xs[nxt][lk+6][lm]=x1n.z; xs[nxt][lk+7][lm]=x1n.w;
            *(float4*)&as_[nxt][akk][ar] = a4n;
        }
        __syncthreads();
    }
    *(float4*)(g_xa + (size_t)(m0+mm)*256 + br*32 + rb)   = make_float4(acc[0],acc[1],acc[2],acc[3]);
    *(float4*)(g_xa + (size_t)(m0+mm)*256 + br*32 + rb+4) = make_float4(acc[4],acc[5],acc[6],acc[7]);
}

// ------- Kernel 3: heads[br] = base(br) + xa_br @ B_br, head layout -------
__global__ void __launch_bounds__(256) k_expand(
    const float* B0, const float* B1, const float* B2, const float* B3,
    const float* B4, const float* B5, const float* B6, const float* B7)
{
    const int br = blockIdx.z;
    const float* Bm;
    switch (br) { case 0: Bm=B0; break; case 1: Bm=B1; break; case 2: Bm=B2; break; case 3: Bm=B3; break;
                  case 4: Bm=B4; break; case 5: Bm=B5; break; case 6: Bm=B6; break; default: Bm=B7; }
    const int baseIdx = (br == 2 || br == 7) ? 2 : ((br == 1 || br == 4 || br == 6) ? 1 : 0);
    const float* tb = g_t + (size_t)baseIdx * 2048u * 1024u;

    const int m0 = blockIdx.y * 64, n0 = blockIdx.x * 64;
    __shared__ __align__(16) float xaS[32][68];
    __shared__ __align__(16) float bS[32][68];

    const int t = threadIdx.x;
    {
        const int m = t >> 2, rr = (t & 3) * 8;
        float4 v0 = *(const float4*)(g_xa + (size_t)(m0+m)*256 + br*32 + rr);
        float4 v1 = *(const float4*)(g_xa + (size_t)(m0+m)*256 + br*32 + rr + 4);
        xaS[rr+0][m]=v0.x; xaS[rr+1][m]=v0.y; xaS[rr+2][m]=v0.z; xaS[rr+3][m]=v0.w;
        xaS[rr+4][m]=v1.x; xaS[rr+5][m]=v1.y; xaS[rr+6][m]=v1.z; xaS[rr+7][m]=v1.w;
    }
    {
        const int r = t >> 3, nn = (t & 7) * 8;
        *(float4*)&bS[r][nn]   = *(const float4*)(Bm + (size_t)r*1024 + n0 + nn);
        *(float4*)&bS[r][nn+4] = *(const float4*)(Bm + (size_t)r*1024 + n0 + nn + 4);
    }
    __syncthreads();

    const int ty = t >> 4, tx = t & 15;
    float acc[4][4];
#pragma unroll
    for (int i = 0; i < 4; i++)
#pragma unroll
        for (int j = 0; j < 4; j++) acc[i][j] = 0.f;
#pragma unroll
    for (int r = 0; r < 32; r++) {
        float4 a4 = *(const float4*)&xaS[r][ty*4];
        float4 b4 = *(const float4*)&bS[r][tx*4];
        acc[0][0]+=a4.x*b4.x; acc[0][1]+=a4.x*b4.y; acc[0][2]+=a4.x*b4.z; acc[0][3]+=a4.x*b4.w;
        acc[1][0]+=a4.y*b4.x; acc[1][1]+=a4.y*b4.y; acc[1][2]+=a4.y*b4.z; acc[1][3]+=a4.y*b4.w;
        acc[2][0]+=a4.z*b4.x; acc[2][1]+=a4.z*b4.y; acc[2][2]+=a4.z*b4.z; acc[2][3]+=a4.z*b4.w;
        acc[3][0]+=a4.w*b4.x; acc[3][1]+=a4.w*b4.y; acc[3][2]+=a4.w*b4.z; acc[3][3]+=a4.w*b4.w;
    }

    const int h = blockIdx.x;
#pragma unroll
    for (int i = 0; i < 4; i++) {
        const int m = m0 + ty*4 + i, b_ = m >> 10, s = m & 1023;
        float4 base = *(const float4*)(tb + (size_t)m*1024 + n0 + tx*4);
        float4 o;
        o.x=acc[i][0]+base.x; o.y=acc[i][1]+base.y; o.z=acc[i][2]+base.z; o.w=acc[i][3]+base.w;
        *(float4*)(g_heads + (((size_t)br*32 + b_*16 + h)*1024 + s)*64 + tx*4) = o;
    }
}

// ---------------- attention helpers ----------------
__device__ __forceinline__ float wredmax(float v) {
#pragma unroll
    for (int o = 16; o > 0; o >>= 1) v = fmaxf(v, __shfl_xor_sync(0xffffffffu, v, o));
    return v;
}
__device__ __forceinline__ float wredsum(float v) {
#pragma unroll
    for (int o = 16; o > 0; o >>= 1) v += __shfl_xor_sync(0xffffffffu, v, o);
    return v;
}
// mapped-uint -> float (inverse of the sign-flip monotone map)
__device__ __forceinline__ float unfmap(unsigned m) {
    return __uint_as_float((m & 0x80000000u) ? (m ^ 0x80000000u) : ~m);
}
// predicated count: c += (s >= thr) on FSETP(alu) + @p FADD(fma)
__device__ __forceinline__ void cadd(float& c, float s, float thr) {
    asm("{ .reg .pred p; setp.ge.f32 p, %1, %2; @p add.f32 %0, %0, 0F3F800000; }"
        : "+f"(c) : "f"(s), "f"(thr));
}

// ---------------- Kernel 4a: phase A (top-k keep bitmask) ----------------
#define A_OFF_KT   0
#define A_OFF_VT   8704
#define A_OFF_QV   (2*8704)
#define A_OFF_MASK (A_OFF_QV + 64*68)
#define A_SMEM_BYTES ((A_OFF_MASK + 1024) * 4)   // 91,136 B

__global__ void __launch_bounds__(512) k_attA(const float* __restrict__ am)
{
    extern __shared__ float smf[];
    float* ktile = smf + A_OFF_KT;
    float* vtile = smf + A_OFF_VT;
    float* qv    = smf + A_OFF_QV;
    float* maskS = smf + A_OFF_MASK;

    const int t = threadIdx.x;
    const int head = blockIdx.y;
    const int qt = blockIdx.x;
    const int q0 = qt * 64;
    const int b_ = head >> 4;

    for (int i = t; i < 1024; i += 512) maskS[i] = am[b_*1024 + i];

    const size_t hs = (size_t)1024 * 64;
    const float* Tqs = g_heads + (3u*32 + head)*hs;
    const float* Tks = g_heads + (4u*32 + head)*hs;

    {   // load 64 qs rows
        const int q = t >> 3, d = (t & 7) * 8;
        *(float4*)&qv[q*68 + d]     = *(const float4*)(Tqs + (size_t)(q0 + q)*64 + d);
        *(float4*)&qv[q*68 + d + 4] = *(const float4*)(Tqs + (size_t)(q0 + q)*64 + d + 4);
    }
    __syncthreads();

    const int qp = t >> 5, kb = t & 31;
    unsigned* gk = g_keep + (((size_t)head*16 + qt)*64)*32;
#pragma unroll 1
    for (int pass = 0; pass < 2; pass++) {
        const int qA = pass*32 + 2*qp, qB = qA + 1;
        float sv0[32], sv1[32];          // raw float scores (no fmap)

        {   // prologue: tile 0 -> ktile
            const int kloc = t >> 2, dd = (t & 3) * 16;
            const float* src = Tks + (size_t)kloc*64 + dd;
            float* dst = ktile + kloc*68 + dd;
#pragma unroll
            for (int jj = 0; jj < 4; jj++) *(float4*)(dst + jj*4) = *(const float4*)(src + jj*4);
        }
        __syncthreads();

        // fully unrolled tile loop (static indices -> registers)
#pragma unroll
        for (int kt = 0; kt < 8; kt++) {
            float* cur = (kt & 1) ? vtile : ktile;
            float* nxt = (kt & 1) ? ktile : vtile;
            if (kt < 7) {
                const int kloc = t >> 2, dd = (t & 3) * 16;
                const float* src = Tks + ((size_t)(kt+1)*128 + kloc)*64 + dd;
                float* dst = nxt + kloc*68 + dd;
#pragma unroll
                for (int jj = 0; jj < 4; jj++) *(float4*)(dst + jj*4) = *(const float4*)(src + jj*4);
            }
            float s0[4] = {0.f,0.f,0.f,0.f}, s1[4] = {0.f,0.f,0.f,0.f};
            const float4* q0v = (const float4*)(qv + qA*68);
            const float4* q1v = (const float4*)(qv + qB*68);
#pragma unroll
            for (int d4 = 0; d4 < 16; d4++) {
                const float4 f0 = q0v[d4], f1 = q1v[d4];
#pragma unroll
                for (int j = 0; j < 4; j++) {
                    const float4 kf = *(const float4*)(cur + (kb + 32*j)*68 + d4*4);
                    s0[j] += f0.x*kf.x + f0.y*kf.y + f0.z*kf.z + f0.w*kf.w;
                    s1[j] += f1.x*kf.x + f1.y*kf.y + f1.z*kf.z + f1.w*kf.w;
                }
            }
#pragma unroll
            for (int j = 0; j < 4; j++) {
                const float mv = maskS[kt*128 + 32*j + kb];
                sv0[kt*4+j] = s0[j] * 0.125f + mv;
                sv1[kt*4+j] = s1[j] * 0.125f + mv;
            }
            __syncthreads();
        }

        // dual exact kth-largest: uint bisection bounds, float-domain counting
        // (count moves to FSETP+predicated-FADD: 1 alu + 1 fma per element)
        unsigned lo0 = 0u, hi0 = 0xFFFFFFFFu, lo1 = 0u, hi1 = 0xFFFFFFFFu;
#pragma unroll 1
        for (int it = 0; it < 32; it++) {
            const unsigned d0 = hi0 - lo0, d1 = hi1 - lo1;
            const unsigned mid0 = lo0 + (d0 >> 1) + (d0 & 1u);
            const unsigned mid1 = lo1 + (d1 >> 1) + (d1 & 1u);
            const float mf0 = unfmap(mid0), mf1 = unfmap(mid1);
            float c0 = 0.f, c1 = 0.f;
#pragma unroll
            for (int i = 0; i < 32; i++) {
                cadd(c0, sv0[i], mf0);
                cadd(c1, sv1[i], mf1);
            }
            // pack: c0 + 2048*c1 (both warp-sums < 2048; exact in fp32)
            const float packed = wredsum(c0 + c1 * 2048.0f);
            const float t1f = floorf(packed * (1.0f/2048.0f));
            const float t0f = packed - t1f * 2048.0f;
            if (t0f >= (float)TOPK) lo0 = mid0; else hi0 = mid0 - 1u;
            if (t1f >= (float)TOPK) lo1 = mid1; else hi1 = mid1 - 1u;
        }
        const float lof0 = unfmap(lo0), lof1 = unfmap(lo1);
#pragma unroll
        for (int i = 0; i < 32; i++) {
            const unsigned b0 = __ballot_sync(0xffffffffu, sv0[i] >= lof0);
            const unsigned b1 = __ballot_sync(0xffffffffu, sv1[i] >= lof1);
            if (kb == 0) { gk[qA*32 + i] = b0; gk[qB*32 + i] = b1; }
        }
        __syncthreads();
    }
}

// ---------------- Kernel 4b: phases B/C (z selects branch) ----------------
#define OFF_KT   0
#define OFF_VT   8704
#define OFF_QV   (2*8704)
#define OFF_MASK (OFF_QV + 64*68)
#define OFF_PBUF (OFF_MASK + 1024)
#define OFF_OA   (OFF_PBUF + 64*128)
#define OFF_FAC  (OFF_OA + 64*68)
#define OFF_LSH  (OFF_FAC + 64)
#define OFF_KEEP (OFF_LSH + 64)
#define BC_SMEM_BYTES ((OFF_KEEP + 64*32) * 4)   // 150,016 B

template<bool KEEP>
__device__ void attn_phase(
    const int t,
    const float* __restrict__ qptr, const float* __restrict__ kptr,
    const float* __restrict__ vptr, const float* __restrict__ maskS,
    float* qv, float* ktile, float* vtile, float* pbuf,
    const unsigned* __restrict__ keepm, float* fac, float* l_sh, float* oacc)
{
    {
        const int q = t >> 3, d = (t & 7) * 8;
        *(float4*)&qv[q*68 + d]     = *(const float4*)(qptr + (size_t)q*64 + d);
        *(float4*)&qv[q*68 + d + 4] = *(const float4*)(qptr + (size_t)q*64 + d + 4);
    }
    for (int i = t; i < 64*68; i += 512) oacc[i] = 0.f;

    float o[8][4];
#pragma unroll
    for (int i = 0; i < 8; i++)
#pragma unroll
        for (int j = 0; j < 4; j++) o[i][j] = 0.f;

    const int w  = t >> 5;
    const int kb = t & 31;
    const int dg = t & 15, kg = (t >> 4) & 3, qg = t >> 6;
    float m_[4], l_[4];
#pragma unroll
    for (int qi = 0; qi < 4; qi++) { m_[qi] = -1e30f; l_[qi] = 0.f; }
    __syncthreads();

    for (int kt = 0; kt < 8; kt++) {
        {
            const int kloc = t >> 2, dd = (t & 3) * 16;
            const float* ksrc = kptr + ((size_t)kt*128 + kloc)*64 + dd;
            const float* vsrc = vptr + ((size_t)kt*128 + kloc)*64 + dd;
            float4 kr[4], vr[4];
#pragma unroll
            for (int jj = 0; jj < 4; jj++) kr[jj] = *(const float4*)(ksrc + jj*4);
#pragma unroll
            for (int jj = 0; jj < 4; jj++) vr[jj] = *(const float4*)(vsrc + jj*4);
            float* kdst = ktile + kloc*68 + dd;
            float* vdst = vtile + kloc*68 + dd;
#pragma unroll
            for (int jj = 0; jj < 4; jj++) *(float4*)(kdst + jj*4) = kr[jj];
#pragma unroll
            for (int jj = 0; jj < 4; jj++) *(float4*)(vdst + jj*4) = vr[jj];
        }
        __syncthreads();

        float s[4][4];
#pragma unroll
        for (int qi = 0; qi < 4; qi++)
#pragma unroll
            for (int j = 0; j < 4; j++) s[qi][j] = 0.f;
#pragma unroll
        for (int d4 = 0; d4 < 16; d4++) {
            float4 qf[4];
#pragma unroll
            for (int qi = 0; qi < 4; qi++)
                qf[qi] = *(const float4*)(qv + (4*w + qi)*68 + d4*4);
#pragma unroll
            for (int j = 0; j < 4; j++) {
                const float4 kf = *(const float4*)(ktile + (kb + 32*j)*68 + d4*4);
#pragma unroll
                for (int qi = 0; qi < 4; qi++)
                    s[qi][j] += qf[qi].x*kf.x + qf[qi].y*kf.y + qf[qi].z*kf.z + qf[qi].w*kf.w;
            }
        }
#pragma unroll
        for (int qi = 0; qi < 4; qi++) {
            bool kp[4];
            float tmx = -1e30f;
#pragma unroll
            for (int j = 0; j < 4; j++) {
                const int key = kt*128 + 32*j + kb;
                float sv = s[qi][j] * 0.125f + maskS[key];
                if (KEEP) {
                    kp[j] = (keepm[(4*w + qi)*32 + kt*4 + j] >> kb) & 1u;
                    if (!kp[j]) sv = -1e30f;
                } else kp[j] = true;
                s[qi][j] = sv;
                tmx = fmaxf(tmx, sv);
            }
            tmx = wredmax(tmx);
            const float nm = fmaxf(m_[qi], tmx);
            const float fr = __expf(m_[qi] - nm);
            m_[qi] = nm;
            if (kb == 0) fac[4*w + qi] = fr;
            float ps = 0.f;
#pragma unroll
            for (int j = 0; j < 4; j++) {
                float p = __expf(s[qi][j] - nm);
                if (KEEP && !kp[j]) p = 0.f;
                pbuf[(4*w + qi)*128 + 32*j + kb] = p;
                ps += p;
            }
            ps = wredsum(ps);
            l_[qi] = l_[qi] * fr + ps;
        }
        __syncthreads();

        {
            float fq[8];
#pragma unroll
            for (int qi = 0; qi < 8; qi++) fq[qi] = fac[8*qg + qi];
#pragma unroll
            for (int qi = 0; qi < 8; qi++) {
                o[qi][0]*=fq[qi]; o[qi][1]*=fq[qi]; o[qi][2]*=fq[qi]; o[qi][3]*=fq[qi];
            }
#pragma unroll
            for (int kk4 = 0; kk4 < 8; kk4++) {
                const int base2 = kg*32 + kk4*4;
                const float4 v0 = *(const float4*)(vtile + (base2+0)*68 + dg*4);
                const float4 v1 = *(const float4*)(vtile + (base2+1)*68 + dg*4);
                const float4 v2 = *(const float4*)(vtile + (base2+2)*68 + dg*4);
                const float4 v3 = *(const float4*)(vtile + (base2+3)*68 + dg*4);
#pragma unroll
                for (int qi = 0; qi < 8; qi++) {
                    const float4 p4 = *(const float4*)(pbuf + (8*qg + qi)*128 + base2);
                    o[qi][0] += p4.x*v0.x + p4.y*v1.x + p4.z*v2.x + p4.w*v3.x;
                    o[qi][1] += p4.x*v0.y + p4.y*v1.y + p4.z*v2.y + p4.w*v3.y;
                    o[qi][2] += p4.x*v0.z + p4.y*v1.z + p4.z*v2.z + p4.w*v3.z;
                    o[qi][3] += p4.x*v0.w + p4.y*v1.w + p4.z*v2.w + p4.w*v3.w;
                }
            }
        }
        __syncthreads();
    }

    if (kb == 0) {
#pragma unroll
        for (int qi = 0; qi < 4; qi++) l_sh[4*w + qi] = l_[qi];
    }
    for (int turn = 0; turn < 4; turn++) {
        if (kg == turn) {
#pragma unroll
            for (int qi = 0; qi < 8; qi++) {
                float* dst = oacc + (8*qg + qi)*68 + dg*4;
                dst[0]+=o[qi][0]; dst[1]+=o[qi][1]; dst[2]+=o[qi][2]; dst[3]+=o[qi][3];
            }
        }
        __syncthreads();
    }
    for (int i = t; i < 64*64; i += 512) {
        const int qq = i >> 6, d = i & 63;
        oacc[qq*68 + d] *= 0.5f / l_sh[qq];
    }
    __syncthreads();
}

__global__ void __launch_bounds__(512) k_attBC(const float* __restrict__ am)
{
    extern __shared__ float smf[];
    float* ktile = smf + OFF_KT;
    float* vtile = smf + OFF_VT;
    float* qv    = smf + OFF_QV;
    float* maskS = smf + OFF_MASK;
    float* pbuf  = smf + OFF_PBUF;
    float* oacc  = smf + OFF_OA;
    float* fac   = smf + OFF_FAC;
    float* l_sh  = smf + OFF_LSH;
    unsigned* keepm = (unsigned*)(smf + OFF_KEEP);

    const int t = threadIdx.x;
    const int head = blockIdx.y;
    const int qt = blockIdx.x;
    const int q0 = qt * 64;
    const int b_ = head >> 4;
    const int z = blockIdx.z;       // 0 = est branch, 1 = sparse branch

    for (int i = t; i < 1024; i += 512) maskS[i] = am[b_*1024 + i];

    const size_t hs = (size_t)1024 * 64;
    const float *Tq_, *Tk_, *Tv_;
    float* dstPart;
    if (z == 0) {
        Tq_ = g_heads + (5u*32 + head)*hs;  // qa
        Tk_ = g_heads + (6u*32 + head)*hs;  // ka
        Tv_ = g_heads + (7u*32 + head)*hs;  // va
        dstPart = g_pb;
    } else {
        Tq_ = g_heads + (0u*32 + head)*hs;  // q
        Tk_ = g_heads + (1u*32 + head)*hs;  // k
        Tv_ = g_heads + (2u*32 + head)*hs;  // v
        dstPart = g_pc;
        const unsigned* gk = g_keep + (((size_t)head*16 + qt)*64)*32;
        for (int i = t; i < 64*32; i += 512) keepm[i] = gk[i];
    }
    __syncthreads();

    if (z == 0)
        attn_phase<false>(t, Tq_ + (size_t)q0*64, Tk_, Tv_, maskS,
                          qv, ktile, vtile, pbuf, keepm, fac, l_sh, oacc);
    else
        attn_phase<true>(t, Tq_ + (size_t)q0*64, Tk_, Tv_, maskS,
                         qv, ktile, vtile, pbuf, keepm, fac, l_sh, oacc);

    for (int i = t; i < 64*64; i += 512) {
        const int qq = i >> 6, d = i & 63;
        dstPart[((size_t)(b_*1024 + q0 + qq))*1024 + (head & 15)*64 + d] = oacc[qq*68 + d];
    }
}

// ---------------- Kernel 5: merge partials ----------------
__global__ void __launch_bounds__(256) k_merge(float* __restrict__ out) {
    const size_t i = ((size_t)blockIdx.x * 256 + threadIdx.x) * 4;
    float4 a = *(const float4*)(g_pb + i);
    float4 b = *(const float4*)(g_pc + i);
    float4 o;
    o.x = a.x + b.x; o.y = a.y + b.y; o.z = a.z + b.z; o.w = a.w + b.w;
    *(float4*)(out + i) = o;
}

// ---------------- host ----------------
extern "C" void kernel_launch(void* const* d_in, const int* in_sizes, int n_in,
                              void* d_out, int out_size) {
    const float* x  = (const float*)d_in[0];
    const float* am = (const float*)d_in[1];
    const float* Wq = (const float*)d_in[2]; const float* bq = (const float*)d_in[3];
    const float* Wk = (const float*)d_in[4]; const float* bk = (const float*)d_in[5];
    const float* Wv = (const float*)d_in[6]; const float* bv = (const float*)d_in[7];
    const float* A[8]; const float* Bm[8];
    for (int i = 0; i < 8; i++) { A[i] = (const float*)d_in[8 + 2*i]; Bm[i] = (const float*)d_in[9 + 2*i]; }
    float* out = (float*)d_out;

    cudaFuncSetAttribute(k_attA, cudaFuncAttributeMaxDynamicSharedMemorySize, A_SMEM_BYTES);
    cudaFuncSetAttribute(k_attBC, cudaFuncAttributeMaxDynamicSharedMemorySize, BC_SMEM_BYTES);

    k_base_gemm<<<dim3(8, 16, 3), 256>>>(x, Wq, bq, Wk, bk, Wv, bv);
    k_xa_gemm<<<dim3(32, 8), 256>>>(x, A[0],A[1],A[2],A[3],A[4],A[5],A[6],A[7]);
    k_expand<<<dim3(16, 32, 8), 256>>>(Bm[0],Bm[1],Bm[2],Bm[3],Bm[4],Bm[5],Bm[6],Bm[7]);
    k_attA<<<dim3(16, 32), 512, A_SMEM_BYTES>>>(am);
    k_attBC<<<dim3(16, 32, 2), 512, BC_SMEM_BYTES>>>(am);
    k_merge<<<2048, 256>>>(out);
}

// round 17
// speedup vs baseline: 1.2862x; 1.0277x over previous
#include <cuda_runtime.h>
#include <cstdint>

// B=2, S=1024, H=1024, NH=16, HD=64, R=32, TOPK=128
#define TOPK 128

// device scratch (no allocation allowed)
__device__ __align__(16) float g_t[3u * 2048u * 1024u];         // tq,tk,tv
__device__ __align__(16) float g_xa[2048u * 256u];              // x @ [A0..A7]
__device__ __align__(16) float g_heads[8u * 32u * 1024u * 64u]; // [br][b*16+h][s][d]
__device__ __align__(16) unsigned g_keep[32u * 1024u * 32u];    // [head][q][word]
__device__ __align__(16) float g_pb[2048u * 1024u];             // est-branch partial
__device__ __align__(16) float g_pc[2048u * 1024u];             // sparse-branch partial

// ---- Kernel 1: t_z = x @ W_z + b_z (two-level FFMA, double-buffered) ------
__global__ void __launch_bounds__(256) k_base_gemm(
    const float* __restrict__ x,
    const float* __restrict__ W0, const float* __restrict__ b0,
    const float* __restrict__ W1, const float* __restrict__ b1,
    const float* __restrict__ W2, const float* __restrict__ b2)
{
    const int z = blockIdx.z;
    const float* W    = (z == 0) ? W0 : ((z == 1) ? W1 : W2);
    const float* bias = (z == 0) ? b0 : ((z == 1) ? b1 : b2);
    float* C = g_t + (size_t)z * 2048u * 1024u;

    const int m0 = blockIdx.y * 128, n0 = blockIdx.x * 128;
    __shared__ __align__(16) float As[2][16][128];
    __shared__ __align__(16) float Bs[2][16][128];

    const int t = threadIdx.x, ty = t >> 4, tx = t & 15;
    float acc[8][8], part[8][8];
#pragma unroll
    for (int i = 0; i < 8; i++)
#pragma unroll
        for (int j = 0; j < 8; j++) { acc[i][j] = 0.f; part[i][j] = 0.f; }

    const int am = t >> 1, ak = (t & 1) * 8;
    const int bk = t >> 4, bn = (t & 15) * 8;

    {   // preload tile 0 into buffer 0
        float4 a0 = *(const float4*)(x + (size_t)(m0 + am) * 1024 + ak);
        float4 a1 = *(const float4*)(x + (size_t)(m0 + am) * 1024 + ak + 4);
        float4 w0 = *(const float4*)(W + (size_t)bk * 1024 + n0 + bn);
        float4 w1 = *(const float4*)(W + (size_t)bk * 1024 + n0 + bn + 4);
        As[0][ak + 0][am] = a0.x; As[0][ak + 1][am] = a0.y; As[0][ak + 2][am] = a0.z; As[0][ak + 3][am] = a0.w;
        As[0][ak + 4][am] = a1.x; As[0][ak + 5][am] = a1.y; As[0][ak + 6][am] = a1.z; As[0][ak + 7][am] = a1.w;
        *(float4*)&Bs[0][bk][bn] = w0;  *(float4*)&Bs[0][bk][bn + 4] = w1;
    }
    __syncthreads();

#pragma unroll 1
    for (int kt = 0; kt < 64; kt++) {
        const int cur = kt & 1, nxt = cur ^ 1;
        float4 a0n, a1n, w0n, w1n;
        if (kt < 63) {
            const int k0 = (kt + 1) * 16;
            a0n = *(const float4*)(x + (size_t)(m0 + am) * 1024 + k0 + ak);
            a1n = *(const float4*)(x + (size_t)(m0 + am) * 1024 + k0 + ak + 4);
            w0n = *(const float4*)(W + (size_t)(k0 + bk) * 1024 + n0 + bn);
            w1n = *(const float4*)(W + (size_t)(k0 + bk) * 1024 + n0 + bn + 4);
        }
#pragma unroll
        for (int kk = 0; kk < 16; kk++) {
            float a[8], b[8];
            *(float4*)&a[0] = *(const float4*)&As[cur][kk][ty * 8];
            *(float4*)&a[4] = *(const float4*)&As[cur][kk][ty * 8 + 4];
            *(float4*)&b[0] = *(const float4*)&Bs[cur][kk][tx * 8];
            *(float4*)&b[4] = *(const float4*)&Bs[cur][kk][tx * 8 + 4];
#pragma unroll
            for (int i = 0; i < 8; i++)
#pragma unroll
                for (int j = 0; j < 8; j++) part[i][j] += a[i] * b[j];
        }
        if (kt < 63) {
            As[nxt][ak + 0][am] = a0n.x; As[nxt][ak + 1][am] = a0n.y;
            As[nxt][ak + 2][am] = a0n.z; As[nxt][ak + 3][am] = a0n.w;
            As[nxt][ak + 4][am] = a1n.x; As[nxt][ak + 5][am] = a1n.y;
            As[nxt][ak + 6][am] = a1n.z; As[nxt][ak + 7][am] = a1n.w;
            *(float4*)&Bs[nxt][bk][bn] = w0n;  *(float4*)&Bs[nxt][bk][bn + 4] = w1n;
        }
        if ((kt & 3) == 3) {
#pragma unroll
            for (int i = 0; i < 8; i++)
#pragma unroll
                for (int j = 0; j < 8; j++) { acc[i][j] += part[i][j]; part[i][j] = 0.f; }
        }
        __syncthreads();
    }
#pragma unroll
    for (int i = 0; i < 8; i++) {
        const int row = m0 + ty * 8 + i;
#pragma unroll
        for (int j4 = 0; j4 < 2; j4++) {
            const int col = n0 + tx * 8 + j4 * 4;
            float4 bb = *(const float4*)(bias + col);
            float4 o;
            o.x = acc[i][j4*4+0] + bb.x; o.y = acc[i][j4*4+1] + bb.y;
            o.z = acc[i][j4*4+2] + bb.z; o.w = acc[i][j4*4+3] + bb.w;
            *(float4*)(C + (size_t)row * 1024 + col) = o;
        }
    }
}

// -------- Kernel 2: xa = x @ A_br (double-buffered) --------
__global__ void __launch_bounds__(256) k_xa_gemm(
    const float* __restrict__ x,
    const float* A0, const float* A1, const float* A2, const float* A3,
    const float* A4, const float* A5, const float* A6, const float* A7)
{
    const int br = blockIdx.y;
    const float* A;
    switch (br) { case 0: A=A0; break; case 1: A=A1; break; case 2: A=A2; break; case 3: A=A3; break;
                  case 4: A=A4; break; case 5: A=A5; break; case 6: A=A6; break; default: A=A7; }
    const int m0 = blockIdx.x * 64;
    __shared__ float xs[2][32][64];
    __shared__ __align__(16) float as_[2][32][32];

    const int t = threadIdx.x;
    const int mm = t >> 2, rb = (t & 3) * 8;
    const int lm = t >> 2, lk = (t & 3) * 8;
    const int akk = t >> 3, ar = (t & 7) * 4;

    float acc[8];
#pragma unroll
    for (int j = 0; j < 8; j++) acc[j] = 0.f;

    {   // preload tile 0
        float4 x0 = *(const float4*)(x + (size_t)(m0 + lm) * 1024 + lk);
        float4 x1 = *(const float4*)(x + (size_t)(m0 + lm) * 1024 + lk + 4);
        float4 a4 = *(const float4*)(A + (size_t)akk * 32 + ar);
        xs[0][lk+0][lm]=x0.x; xs[0][lk+1][lm]=x0.y; xs[0][lk+2][lm]=x0.z; xs[0][lk+3][lm]=x0.w;
        xs[0][lk+4][lm]=x1.x; xs[0][lk+5][lm]=x1.y; xs[0][lk+6][lm]=x1.z; xs[0][lk+7][lm]=x1.w;
        *(float4*)&as_[0][akk][ar] = a4;
    }
    __syncthreads();

#pragma unroll 1
    for (int kt = 0; kt < 32; kt++) {
        const int cur = kt & 1, nxt = cur ^ 1;
        float4 x0n, x1n, a4n;
        if (kt < 31) {
            const int k0 = (kt + 1) * 32;
            x0n = *(const float4*)(x + (size_t)(m0 + lm) * 1024 + k0 + lk);
            x1n = *(const float4*)(x + (size_t)(m0 + lm) * 1024 + k0 + lk + 4);
            a4n = *(const float4*)(A + (size_t)(k0 + akk) * 32 + ar);
        }
        float part[8];
#pragma unroll
        for (int j = 0; j < 8; j++) part[j] = 0.f;
#pragma unroll
        for (int kk = 0; kk < 32; kk++) {
            const float xv = xs[cur][kk][mm];
#pragma unroll
            for (int j = 0; j < 8; j++) part[j] += xv * as_[cur][kk][rb + j];
        }
#pragma unroll
        for (int j = 0; j < 8; j++) acc[j] += part[j];
        if (kt < 31) {
            xs[nxt][lk+0][lm]=x0n.x; xs[nxt][lk+1][lm]=x0n.y; xs[nxt][lk+2][lm]=x0n.z; xs[nxt][lk+3][lm]=x0n.w;
            xs[nxt][lk+4][lm]=x1n.x; xs[nxt][lk+5][lm]=x1n.y; xs[nxt][lk+6][lm]=x1n.z; xs[nxt][lk+7][lm]=x1n.w;
            *(float4*)&as_[nxt][akk][ar] = a4n;
        }
        __syncthreads();
    }
    *(float4*)(g_xa + (size_t)(m0+mm)*256 + br*32 + rb)   = make_float4(acc[0],acc[1],acc[2],acc[3]);
    *(float4*)(g_xa + (size_t)(m0+mm)*256 + br*32 + rb+4) = make_float4(acc[4],acc[5],acc[6],acc[7]);
}

// ------- Kernel 3: heads[br] = base(br) + xa_br @ B_br, head layout -------
__global__ void __launch_bounds__(256) k_expand(
    const float* B0, const float* B1, const float* B2, const float* B3,
    const float* B4, const float* B5, const float* B6, const float* B7)
{
    const int br = blockIdx.z;
    const float* Bm;
    switch (br) { case 0: Bm=B0; break; case 1: Bm=B1; break; case 2: Bm=B2; break; case 3: Bm=B3; break;
                  case 4: Bm=B4; break; case 5: Bm=B5; break; case 6: Bm=B6; break; default: Bm=B7; }
    const int baseIdx = (br == 2 || br == 7) ? 2 : ((br == 1 || br == 4 || br == 6) ? 1 : 0);
    const float* tb = g_t + (size_t)baseIdx * 2048u * 1024u;

    const int m0 = blockIdx.y * 64, n0 = blockIdx.x * 64;
    __shared__ __align__(16) float xaS[32][68];
    __shared__ __align__(16) float bS[32][68];

    const int t = threadIdx.x;
    {
        const int m = t >> 2, rr = (t & 3) * 8;
        float4 v0 = *(const float4*)(g_xa + (size_t)(m0+m)*256 + br*32 + rr);
        float4 v1 = *(const float4*)(g_xa + (size_t)(m0+m)*256 + br*32 + rr + 4);
        xaS[rr+0][m]=v0.x; xaS[rr+1][m]=v0.y; xaS[rr+2][m]=v0.z; xaS[rr+3][m]=v0.w;
        xaS[rr+4][m]=v1.x; xaS[rr+5][m]=v1.y; xaS[rr+6][m]=v1.z; xaS[rr+7][m]=v1.w;
    }
    {
        const int r = t >> 3, nn = (t & 7) * 8;
        *(float4*)&bS[r][nn]   = *(const float4*)(Bm + (size_t)r*1024 + n0 + nn);
        *(float4*)&bS[r][nn+4] = *(const float4*)(Bm + (size_t)r*1024 + n0 + nn + 4);
    }
    __syncthreads();

    const int ty = t >> 4, tx = t & 15;
    float acc[4][4];
#pragma unroll
    for (int i = 0; i < 4; i++)
#pragma unroll
        for (int j = 0; j < 4; j++) acc[i][j] = 0.f;
#pragma unroll
    for (int r = 0; r < 32; r++) {
        float4 a4 = *(const float4*)&xaS[r][ty*4];
        float4 b4 = *(const float4*)&bS[r][tx*4];
        acc[0][0]+=a4.x*b4.x; acc[0][1]+=a4.x*b4.y; acc[0][2]+=a4.x*b4.z; acc[0][3]+=a4.x*b4.w;
        acc[1][0]+=a4.y*b4.x; acc[1][1]+=a4.y*b4.y; acc[1][2]+=a4.y*b4.z; acc[1][3]+=a4.y*b4.w;
        acc[2][0]+=a4.z*b4.x; acc[2][1]+=a4.z*b4.y; acc[2][2]+=a4.z*b4.z; acc[2][3]+=a4.z*b4.w;
        acc[3][0]+=a4.w*b4.x; acc[3][1]+=a4.w*b4.y; acc[3][2]+=a4.w*b4.z; acc[3][3]+=a4.w*b4.w;
    }

    const int h = blockIdx.x;
#pragma unroll
    for (int i = 0; i < 4; i++) {
        const int m = m0 + ty*4 + i, b_ = m >> 10, s = m & 1023;
        float4 base = *(const float4*)(tb + (size_t)m*1024 + n0 + tx*4);
        float4 o;
        o.x=acc[i][0]+base.x; o.y=acc[i][1]+base.y; o.z=acc[i][2]+base.z; o.w=acc[i][3]+base.w;
        *(float4*)(g_heads + (((size_t)br*32 + b_*16 + h)*1024 + s)*64 + tx*4) = o;
    }
}

// ---------------- attention helpers ----------------
__device__ __forceinline__ float wredsum(float v) {
#pragma unroll
    for (int o = 16; o > 0; o >>= 1) v += __shfl_xor_sync(0xffffffffu, v, o);
    return v;
}
__device__ __forceinline__ float unfmap(unsigned m) {
    return __uint_as_float((m & 0x80000000u) ? (m ^ 0x80000000u) : ~m);
}
__device__ __forceinline__ void cadd(float& c, float s, float thr) {
    asm("{ .reg .pred p; setp.ge.f32 p, %1, %2; @p add.f32 %0, %0, 0F3F800000; }"
        : "+f"(c) : "f"(s), "f"(thr));
}

// ---------------- Kernel 4a: phase A (top-k keep bitmask), 32q CTA ----------
#define A_OFF_KT   0
#define A_OFF_VT   8704
#define A_OFF_QV   (2*8704)
#define A_OFF_MASK (A_OFF_QV + 32*68)
#define A_SMEM_BYTES ((A_OFF_MASK + 1024) * 4)   // 82,432 B

__global__ void __launch_bounds__(512) k_attA(const float* __restrict__ am)
{
    extern __shared__ float smf[];
    float* ktile = smf + A_OFF_KT;
    float* vtile = smf + A_OFF_VT;
    float* qv    = smf + A_OFF_QV;
    float* maskS = smf + A_OFF_MASK;

    const int t = threadIdx.x;
    const int head = blockIdx.y;
    const int q0 = blockIdx.x * 32;
    const int b_ = head >> 4;

    for (int i = t; i < 1024; i += 512) maskS[i] = am[b_*1024 + i];

    const size_t hs = (size_t)1024 * 64;
    const float* Tqs = g_heads + (3u*32 + head)*hs;
    const float* Tks = g_heads + (4u*32 + head)*hs;

    {   // load 32 qs rows (16 threads/row)
        const int q = t >> 4, d = (t & 15) * 4;
        *(float4*)&qv[q*68 + d] = *(const float4*)(Tqs + (size_t)(q0 + q)*64 + d);
    }
    __syncthreads();

    const int qp = t >> 5, kb = t & 31;
    const int qA = 2*qp, qB = qA + 1;
    float sv0[32], sv1[32];

    {   // prologue: tile 0 -> ktile
        const int kloc = t >> 2, dd = (t & 3) * 16;
        const float* src = Tks + (size_t)kloc*64 + dd;
        float* dst = ktile + kloc*68 + dd;
#pragma unroll
        for (int jj = 0; jj < 4; jj++) *(float4*)(dst + jj*4) = *(const float4*)(src + jj*4);
    }
    __syncthreads();

    // fully unrolled tile loop (static indices -> registers)
#pragma unroll
    for (int kt = 0; kt < 8; kt++) {
        float* cur = (kt & 1) ? vtile : ktile;
        float* nxt = (kt & 1) ? ktile : vtile;
        if (kt < 7) {
            const int kloc = t >> 2, dd = (t & 3) * 16;
            const float* src = Tks + ((size_t)(kt+1)*128 + kloc)*64 + dd;
            float* dst = nxt + kloc*68 + dd;
#pragma unroll
            for (int jj = 0; jj < 4; jj++) *(float4*)(dst + jj*4) = *(const float4*)(src + jj*4);
        }
        float s0[4] = {0.f,0.f,0.f,0.f}, s1[4] = {0.f,0.f,0.f,0.f};
        const float4* q0v = (const float4*)(qv + qA*68);
        const float4* q1v = (const float4*)(qv + qB*68);
#pragma unroll
        for (int d4 = 0; d4 < 16; d4++) {
            const float4 f0 = q0v[d4], f1 = q1v[d4];
#pragma unroll
            for (int j = 0; j < 4; j++) {
                const float4 kf = *(const float4*)(cur + (kb + 32*j)*68 + d4*4);
                s0[j] += f0.x*kf.x + f0.y*kf.y + f0.z*kf.z + f0.w*kf.w;
                s1[j] += f1.x*kf.x + f1.y*kf.y + f1.z*kf.z + f1.w*kf.w;
            }
        }
#pragma unroll
        for (int j = 0; j < 4; j++) {
            const float mv = maskS[kt*128 + 32*j + kb];
            sv0[kt*4+j] = s0[j] * 0.125f + mv;
            sv1[kt*4+j] = s1[j] * 0.125f + mv;
        }
        __syncthreads();
    }

    // dual exact kth-largest: uint bisection, float-domain counting
    unsigned lo0 = 0u, hi0 = 0xFFFFFFFFu, lo1 = 0u, hi1 = 0xFFFFFFFFu;
#pragma unroll 1
    for (int it = 0; it < 32; it++) {
        const unsigned d0 = hi0 - lo0, d1 = hi1 - lo1;
        const unsigned mid0 = lo0 + (d0 >> 1) + (d0 & 1u);
        const unsigned mid1 = lo1 + (d1 >> 1) + (d1 & 1u);
        const float mf0 = unfmap(mid0), mf1 = unfmap(mid1);
        float c0 = 0.f, c1 = 0.f;
#pragma unroll
        for (int i = 0; i < 32; i++) {
            cadd(c0, sv0[i], mf0);
            cadd(c1, sv1[i], mf1);
        }
        const float packed = wredsum(c0 + c1 * 2048.0f);
        const float t1f = floorf(packed * (1.0f/2048.0f));
        const float t0f = packed - t1f * 2048.0f;
        if (t0f >= (float)TOPK) lo0 = mid0; else hi0 = mid0 - 1u;
        if (t1f >= (float)TOPK) lo1 = mid1; else hi1 = mid1 - 1u;
    }
    const float lof0 = unfmap(lo0), lof1 = unfmap(lo1);
    unsigned* gk = g_keep + ((size_t)head*1024)*32;
#pragma unroll
    for (int i = 0; i < 32; i++) {
        const unsigned b0 = __ballot_sync(0xffffffffu, sv0[i] >= lof0);
        const unsigned b1 = __ballot_sync(0xffffffffu, sv1[i] >= lof1);
        if (kb == 0) { gk[(q0 + qA)*32 + i] = b0; gk[(q0 + qB)*32 + i] = b1; }
    }
}

// ---------------- Kernel 4b: phases B/C (z selects branch) ----------------
// Softmax without max-subtraction (shift-invariant; mask additive, scores tiny)
#define OFF_KT   0
#define OFF_VT   8704
#define OFF_QV   (2*8704)
#define OFF_MASK (OFF_QV + 64*68)
#define OFF_PBUF (OFF_MASK + 1024)
#define OFF_OA   (OFF_PBUF + 64*128)
#define OFF_LSH  (OFF_OA + 64*68)
#define OFF_KEEP (OFF_LSH + 64)
#define BC_SMEM_BYTES ((OFF_KEEP + 64*32) * 4)   // 149,760 B

template<bool KEEP>
__device__ void attn_phase(
    const int t,
    const float* __restrict__ qptr, const float* __restrict__ kptr,
    const float* __restrict__ vptr, const float* __restrict__ maskS,
    float* qv, float* ktile, float* vtile, float* pbuf,
    const unsigned* __restrict__ keepm, float* l_sh, float* oacc)
{
    {
        const int q = t >> 3, d = (t & 7) * 8;
        *(float4*)&qv[q*68 + d]     = *(const float4*)(qptr + (size_t)q*64 + d);
        *(float4*)&qv[q*68 + d + 4] = *(const float4*)(qptr + (size_t)q*64 + d + 4);
    }
    for (int i = t; i < 64*68; i += 512) oacc[i] = 0.f;

    float o[8][4];
#pragma unroll
    for (int i = 0; i < 8; i++)
#pragma unroll
        for (int j = 0; j < 4; j++) o[i][j] = 0.f;

    const int w  = t >> 5;
    const int kb = t & 31;
    const int dg = t & 15, kg = (t >> 4) & 3, qg = t >> 6;
    float l_[4];
#pragma unroll
    for (int qi = 0; qi < 4; qi++) l_[qi] = 0.f;
    __syncthreads();

    for (int kt = 0; kt < 8; kt++) {
        {
            const int kloc = t >> 2, dd = (t & 3) * 16;
            const float* ksrc = kptr + ((size_t)kt*128 + kloc)*64 + dd;
            const float* vsrc = vptr + ((size_t)kt*128 + kloc)*64 + dd;
            float4 kr[4], vr[4];
#pragma unroll
            for (int jj = 0; jj < 4; jj++) kr[jj] = *(const float4*)(ksrc + jj*4);
#pragma unroll
            for (int jj = 0; jj < 4; jj++) vr[jj] = *(const float4*)(vsrc + jj*4);
            float* kdst = ktile + kloc*68 + dd;
            float* vdst = vtile + kloc*68 + dd;
#pragma unroll
            for (int jj = 0; jj < 4; jj++) *(float4*)(kdst + jj*4) = kr[jj];
#pragma unroll
            for (int jj = 0; jj < 4; jj++) *(float4*)(vdst + jj*4) = vr[jj];
        }
        __syncthreads();

        float s[4][4];
#pragma unroll
        for (int qi = 0; qi < 4; qi++)
#pragma unroll
            for (int j = 0; j < 4; j++) s[qi][j] = 0.f;
#pragma unroll
        for (int d4 = 0; d4 < 16; d4++) {
            float4 qf[4];
#pragma unroll
            for (int qi = 0; qi < 4; qi++)
                qf[qi] = *(const float4*)(qv + (4*w + qi)*68 + d4*4);
#pragma unroll
            for (int j = 0; j < 4; j++) {
                const float4 kf = *(const float4*)(ktile + (kb + 32*j)*68 + d4*4);
#pragma unroll
                for (int qi = 0; qi < 4; qi++)
                    s[qi][j] += qf[qi].x*kf.x + qf[qi].y*kf.y + qf[qi].z*kf.z + qf[qi].w*kf.w;
            }
        }
#pragma unroll
        for (int qi = 0; qi < 4; qi++) {
            float ps = 0.f;
#pragma unroll
            for (int j = 0; j < 4; j++) {
                const int key = kt*128 + 32*j + kb;
                float p;
                if (KEEP) {
                    const bool kp = (keepm[(4*w + qi)*32 + kt*4 + j] >> kb) & 1u;
                    p = kp ? __expf(s[qi][j] * 0.125f + maskS[key]) : 0.f;
                } else {
                    p = __expf(s[qi][j] * 0.125f + maskS[key]);
                }
                pbuf[(4*w + qi)*128 + 32*j + kb] = p;
                ps += p;
            }
            l_[qi] += wredsum(ps);
        }
        __syncthreads();

        {
#pragma unroll
            for (int kk4 = 0; kk4 < 8; kk4++) {
                const int base2 = kg*32 + kk4*4;
                const float4 v0 = *(const float4*)(vtile + (base2+0)*68 + dg*4);
                const float4 v1 = *(const float4*)(vtile + (base2+1)*68 + dg*4);
                const float4 v2 = *(const float4*)(vtile + (base2+2)*68 + dg*4);
                const float4 v3 = *(const float4*)(vtile + (base2+3)*68 + dg*4);
#pragma unroll
                for (int qi = 0; qi < 8; qi++) {
                    const float4 p4 = *(const float4*)(pbuf + (8*qg + qi)*128 + base2);
                    o[qi][0] += p4.x*v0.x + p4.y*v1.x + p4.z*v2.x + p4.w*v3.x;
                    o[qi][1] += p4.x*v0.y + p4.y*v1.y + p4.z*v2.y + p4.w*v3.y;
                    o[qi][2] += p4.x*v0.z + p4.y*v1.z + p4.z*v2.z + p4.w*v3.z;
                    o[qi][3] += p4.x*v0.w + p4.y*v1.w + p4.z*v2.w + p4.w*v3.w;
                }
            }
        }
        __syncthreads();
    }

    if (kb == 0) {
#pragma unroll
        for (int qi = 0; qi < 4; qi++) l_sh[4*w + qi] = l_[qi];
    }
    for (int turn = 0; turn < 4; turn++) {
        if (kg == turn) {
#pragma unroll
            for (int qi = 0; qi < 8; qi++) {
                float* dst = oacc + (8*qg + qi)*68 + dg*4;
                dst[0]+=o[qi][0]; dst[1]+=o[qi][1]; dst[2]+=o[qi][2]; dst[3]+=o[qi][3];
            }
        }
        __syncthreads();
    }
    for (int i = t; i < 64*64; i += 512) {
        const int qq = i >> 6, d = i & 63;
        oacc[qq*68 + d] *= 0.5f / l_sh[qq];
    }
    __syncthreads();
}

__global__ void __launch_bounds__(512) k_attBC(const float* __restrict__ am)
{
    extern __shared__ float smf[];
    float* ktile = smf + OFF_KT;
    float* vtile = smf + OFF_VT;
    float* qv    = smf + OFF_QV;
    float* maskS = smf + OFF_MASK;
    float* pbuf  = smf + OFF_PBUF;
    float* oacc  = smf + OFF_OA;
    float* l_sh  = smf + OFF_LSH;
    unsigned* keepm = (unsigned*)(smf + OFF_KEEP);

    const int t = threadIdx.x;
    const int head = blockIdx.y;
    const int q0 = blockIdx.x * 64;
    const int b_ = head >> 4;
    const int z = blockIdx.z;       // 0 = est branch, 1 = sparse branch

    for (int i = t; i < 1024; i += 512) maskS[i] = am[b_*1024 + i];

    const size_t hs = (size_t)1024 * 64;
    const float *Tq_, *Tk_, *Tv_;
    float* dstPart;
    if (z == 0) {
        Tq_ = g_heads + (5u*32 + head)*hs;  // qa
        Tk_ = g_heads + (6u*32 + head)*hs;  // ka
        Tv_ = g_heads + (7u*32 + head)*hs;  // va
        dstPart = g_pb;
    } else {
        Tq_ = g_heads + (0u*32 + head)*hs;  // q
        Tk_ = g_heads + (1u*32 + head)*hs;  // k
        Tv_ = g_heads + (2u*32 + head)*hs;  // v
        dstPart = g_pc;
        const unsigned* gk = g_keep + ((size_t)head*1024 + q0)*32;
        for (int i = t; i < 64*32; i += 512) keepm[i] = gk[i];
    }
    __syncthreads();

    if (z == 0)
        attn_phase<false>(t, Tq_ + (size_t)q0*64, Tk_, Tv_, maskS,
                          qv, ktile, vtile, pbuf, keepm, l_sh, oacc);
    else
        attn_phase<true>(t, Tq_ + (size_t)q0*64, Tk_, Tv_, maskS,
                         qv, ktile, vtile, pbuf, keepm, l_sh, oacc);

    for (int i = t; i < 64*64; i += 512) {
        const int qq = i >> 6, d = i & 63;
        dstPart[((size_t)(b_*1024 + q0 + qq))*1024 + (head & 15)*64 + d] = oacc[qq*68 + d];
    }
}

// ---------------- Kernel 5: merge partials ----------------
__global__ void __launch_bounds__(256) k_merge(float* __restrict__ out) {
    const size_t i = ((size_t)blockIdx.x * 256 + threadIdx.x) * 4;
    float4 a = *(const float4*)(g_pb + i);
    float4 b = *(const float4*)(g_pc + i);
    float4 o;
    o.x = a.x + b.x; o.y = a.y + b.y; o.z = a.z + b.z; o.w = a.w + b.w;
    *(float4*)(out + i) = o;
}

// ---------------- host ----------------
extern "C" void kernel_launch(void* const* d_in, const int* in_sizes, int n_in,
                              void* d_out, int out_size) {
    const float* x  = (const float*)d_in[0];
    const float* am = (const float*)d_in[1];
    const float* Wq = (const float*)d_in[2]; const float* bq = (const float*)d_in[3];
    const float* Wk = (const float*)d_in[4]; const float* bk = (const float*)d_in[5];
    const float* Wv = (const float*)d_in[6]; const float* bv = (const float*)d_in[7];
    const float* A[8]; const float* Bm[8];
    for (int i = 0; i < 8; i++) { A[i] = (const float*)d_in[8 + 2*i]; Bm[i] = (const float*)d_in[9 + 2*i]; }
    float* out = (float*)d_out;

    cudaFuncSetAttribute(k_attA, cudaFuncAttributeMaxDynamicSharedMemorySize, A_SMEM_BYTES);
    cudaFuncSetAttribute(k_attBC, cudaFuncAttributeMaxDynamicSharedMemorySize, BC_SMEM_BYTES);

    k_base_gemm<<<dim3(8, 16, 3), 256>>>(x, Wq, bq, Wk, bk, Wv, bv);
    k_xa_gemm<<<dim3(32, 8), 256>>>(x, A[0],A[1],A[2],A[3],A[4],A[5],A[6],A[7]);
    k_expand<<<dim3(16, 32, 8), 256>>>(Bm[0],Bm[1],Bm[2],Bm[3],Bm[4],Bm[5],Bm[6],Bm[7]);
    k_attA<<<dim3(32, 32), 512, A_SMEM_BYTES>>>(am);
    k_attBC<<<dim3(16, 32, 2), 512, BC_SMEM_BYTES>>>(am);
    k_merge<<<2048, 256>>>(out);
}